// round 13
// baseline (speedup 1.0000x reference)
#include <cuda_runtime.h>
#include <math.h>

#define Bq 2
#define Lq 2048
#define Dm 2048
#define NH 16
#define HDv 128
#define KVHv 4
#define NE 8
#define NI 1024
#define Ttok (Bq*Lq)          /* 4096 */
#define KVD (KVHv*HDv)        /* 512  */
#define SLOTS (Ttok*2)        /* 8192 */

// ---------------- scratch ----------------
__device__ float g_h[Ttok*Dm];
__device__ float g_q[Ttok*Dm];
__device__ float g_k[Ttok*KVD];
__device__ float g_v[Ttok*KVD];
__device__ float g_ao[Ttok*Dm];
__device__ float g_g[SLOTS*NI];
__device__ float g_y[SLOTS*Dm];
__device__ float g_scores[Ttok*NE];
__device__ int   g_counts[NE];
__device__ int   g_offsets[NE+1];
__device__ int   g_cursor[NE];
__device__ int   g_top_idx[Ttok*2];
__device__ float g_top_w[Ttok*2];
__device__ int   g_slot_token[SLOTS];
__device__ float g_slot_w[SLOTS];
__device__ int   g_slot_of[Ttok*2];
__device__ float r_wq[Dm*Dm];
__device__ float r_wk[Dm*KVD];
__device__ float r_wv[Dm*KVD];
__device__ float r_wo[Dm*Dm];

__device__ __forceinline__ unsigned f2tf(float x) {
    unsigned r; asm("cvt.rna.tf32.f32 %0, %1;" : "=r"(r) : "f"(x)); return r;
}
__device__ __forceinline__ float f2tff(float x) { return __uint_as_float(f2tf(x)); }
__device__ __forceinline__ void cp16(unsigned d, const void* s) {
    asm volatile("cp.async.cg.shared.global [%0], [%1], 16;" :: "r"(d), "l"(s));
}
__device__ __forceinline__ void cp_commit() {
    asm volatile("cp.async.commit_group;");
}
template<int N> __device__ __forceinline__ void cp_wait() {
    asm volatile("cp.async.wait_group %0;" :: "n"(N));
}
#define MMA_TF32(d0,d1,d2,d3,a0,a1,a2,a3,b0,b1) \
    asm volatile( \
        "mma.sync.aligned.m16n8k8.row.col.f32.tf32.tf32.f32 " \
        "{%0,%1,%2,%3}, {%4,%5,%6,%7}, {%8,%9}, {%0,%1,%2,%3};" \
        : "+f"(d0), "+f"(d1), "+f"(d2), "+f"(d3) \
        : "r"(a0), "r"(a1), "r"(a2), "r"(a3), "r"(b0), "r"(b1))

// ---------------- fused prep: zero counters + round all attention weights ----------------
#define PREP_N0 (Dm*Dm/4)
#define PREP_N1 (Dm*KVD/4)
#define PREP_TOTAL (2*PREP_N0 + 2*PREP_N1)

__global__ void prep_kernel(const float* __restrict__ wq, const float* __restrict__ wk,
                            const float* __restrict__ wv, const float* __restrict__ wo,
                            float* __restrict__ dq, float* __restrict__ dk,
                            float* __restrict__ dv, float* __restrict__ dwo) {
    if (blockIdx.x == 0 && threadIdx.x < NE) {
        g_counts[threadIdx.x] = 0; g_cursor[threadIdx.x] = 0;
    }
    int i = blockIdx.x*256 + threadIdx.x;
    if (i >= PREP_TOTAL) return;
    const float* s; float* d; int j = i;
    if (j < PREP_N0) { s = wq; d = dq; }
    else {
        j -= PREP_N0;
        if (j < PREP_N1) { s = wk; d = dk; }
        else {
            j -= PREP_N1;
            if (j < PREP_N1) { s = wv; d = dv; }
            else { j -= PREP_N1; s = wo; d = dwo; }
        }
    }
    float4 v = ((const float4*)s)[j];
    uint4 u;
    u.x = f2tf(v.x); u.y = f2tf(v.y); u.z = f2tf(v.z); u.w = f2tf(v.w);
    ((uint4*)d)[j] = u;
}

__global__ void rmsnorm_kernel(const float* __restrict__ in,
                               const float* __restrict__ w,
                               float* __restrict__ out) {
    int t = blockIdx.x;
    const float* row = in + (size_t)t*Dm;
    float ss = 0.f;
    for (int i = threadIdx.x; i < Dm; i += 256) { float v = row[i]; ss += v*v; }
    __shared__ float red[8];
    for (int o = 16; o; o >>= 1) ss += __shfl_xor_sync(0xffffffffu, ss, o);
    if ((threadIdx.x & 31) == 0) red[threadIdx.x >> 5] = ss;
    __syncthreads();
    float tot = 0.f;
    #pragma unroll
    for (int i = 0; i < 8; i++) tot += red[i];
    float inv = rsqrtf(tot * (1.f/(float)Dm) + 1e-5f);
    for (int i = threadIdx.x; i < Dm; i += 256)
        out[(size_t)t*Dm + i] = f2tff(row[i] * inv * w[i]);
}

// ---------------- tf32 GEMM, cp.async double-buffered (2-stage) ----------------
#define GA_STRIDE 36
#define GB_STRIDE 136
#define GA_BUF (128*GA_STRIDE)
#define GB_BUF (32*GB_STRIDE)
#define GEMM_SMEM ((2*GA_BUF + 2*GB_BUF)*4)

__global__ void __launch_bounds__(256, 2) tf32_gemm(
    const float* __restrict__ A, const float* __restrict__ B,
    float* __restrict__ C, int M, int N, int K,
    const float* __restrict__ addsrc, int mode,
    const float* __restrict__ B2, float* __restrict__ C2)
{
    extern __shared__ float dsm[];
    float* As = dsm;
    float* Bs = dsm + 2*GA_BUF;
    int cnt, off;
    if (mode == 0) {
        cnt = M; off = 0;
        if (blockIdx.z == 1) { B = B2; C = C2; }
    } else {
        int e = blockIdx.z;
        cnt = g_counts[e]; off = g_offsets[e];
        B += (size_t)e * K * N;
    }
    int bm = blockIdx.y * 128;
    if (bm >= cnt) return;
    int bn = blockIdx.x * 128;
    int tid = threadIdx.x;
    int lane = tid & 31, wid = tid >> 5;
    int warp_m = wid >> 2, warp_n = wid & 3;
    int lq = lane >> 2, lr = lane & 3;

    const float* aptr[4];
    #pragma unroll
    for (int r = 0; r < 4; r++) {
        int row = bm + r*32 + (tid >> 3);
        int re = row < cnt ? row : cnt - 1;
        if (mode == 1)      aptr[r] = g_h + (size_t)g_slot_token[off + re] * K;
        else if (mode == 2) aptr[r] = A + (size_t)(off + re) * K;
        else                aptr[r] = A + (size_t)re * K;
    }
    int ak4 = (tid & 7) * 4;
    int bk  = tid >> 5;
    int bn4 = lane * 4;
    const float* bsrc = B + (size_t)bk*N + bn + bn4;

    unsigned as_sm = (unsigned)__cvta_generic_to_shared(As);
    unsigned bs_sm = (unsigned)__cvta_generic_to_shared(Bs);
    unsigned a_dst0 = as_sm + (((tid>>3)*GA_STRIDE) + ak4)*4u;
    unsigned b_dst0 = bs_sm + ((bk*GB_STRIDE) + bn4)*4u;

    float acc[4][4][4];
    #pragma unroll
    for (int i=0;i<4;i++)
        #pragma unroll
        for(int j=0;j<4;j++)
            #pragma unroll
            for(int c=0;c<4;c++) acc[i][j][c]=0.f;

    int nkt = K >> 5;
    #pragma unroll
    for (int r = 0; r < 4; r++)
        cp16(a_dst0 + (unsigned)(r*32*GA_STRIDE)*4u, aptr[r] + ak4);
    #pragma unroll
    for (int r = 0; r < 4; r++)
        cp16(b_dst0 + (unsigned)(r*8*GB_STRIDE)*4u, bsrc + (size_t)(r*8)*N);
    cp_commit();

    for (int it = 0; it < nkt; it++) {
        int cur = it & 1;
        if (it + 1 < nkt) {
            int nb = (it + 1) & 1;
            int k0 = (it + 1) << 5;
            unsigned ad = a_dst0 + (unsigned)(nb*GA_BUF)*4u;
            unsigned bd = b_dst0 + (unsigned)(nb*GB_BUF)*4u;
            #pragma unroll
            for (int r = 0; r < 4; r++)
                cp16(ad + (unsigned)(r*32*GA_STRIDE)*4u, aptr[r] + k0 + ak4);
            #pragma unroll
            for (int r = 0; r < 4; r++)
                cp16(bd + (unsigned)(r*8*GB_STRIDE)*4u, bsrc + (size_t)(k0 + r*8)*N);
            cp_commit();
            cp_wait<1>();
        } else {
            cp_wait<0>();
        }
        __syncthreads();
        const float* Ac = As + cur*GA_BUF;
        const float* Bc = Bs + cur*GB_BUF;
        #pragma unroll
        for (int ks = 0; ks < 4; ks++) {
            int k8 = ks*8;
            unsigned af[4][4], bf[4][2];
            #pragma unroll
            for (int mt=0; mt<4; mt++) {
                int m0 = warp_m*64 + mt*16;
                const float* p = &Ac[(m0+lq)*GA_STRIDE + k8 + lr];
                af[mt][0] = __float_as_uint(p[0]);
                af[mt][1] = __float_as_uint(p[8*GA_STRIDE]);
                af[mt][2] = __float_as_uint(p[4]);
                af[mt][3] = __float_as_uint(p[8*GA_STRIDE+4]);
            }
            #pragma unroll
            for (int nt=0; nt<4; nt++) {
                int n0 = warp_n*32 + nt*8 + lq;
                bf[nt][0] = __float_as_uint(Bc[(k8+lr)*GB_STRIDE + n0]);
                bf[nt][1] = __float_as_uint(Bc[(k8+4+lr)*GB_STRIDE + n0]);
            }
            #pragma unroll
            for (int mt=0; mt<4; mt++)
                #pragma unroll
                for (int nt=0; nt<4; nt++)
                    MMA_TF32(acc[mt][nt][0], acc[mt][nt][1], acc[mt][nt][2], acc[mt][nt][3],
                             af[mt][0], af[mt][1], af[mt][2], af[mt][3],
                             bf[nt][0], bf[nt][1]);
        }
        __syncthreads();
    }
    #pragma unroll
    for (int mt=0; mt<4; mt++) {
        int row0 = bm + warp_m*64 + mt*16 + lq;
        #pragma unroll
        for (int half=0; half<2; half++) {
            int row = row0 + half*8;
            if (row >= cnt) continue;
            size_t crow = (size_t)(off + row);
            #pragma unroll
            for (int nt=0; nt<4; nt++) {
                int col = bn + warp_n*32 + nt*8 + 2*lr;
                float2 v;
                v.x = acc[mt][nt][half*2+0];
                v.y = acc[mt][nt][half*2+1];
                if (addsrc) {
                    float2 s = *(const float2*)(addsrc + crow*N + col);
                    v.x += s.x; v.y += s.y;
                }
                *(float2*)(C + crow*N + col) = v;
            }
        }
    }
}

// ---------------- fused MoE up-proj: g_g = silu(Xg@W1) * (Xg@W3) ----------------
#define MA_STRIDE 36
#define MB_STRIDE 72
#define MA_BUF (128*MA_STRIDE)
#define MB_BUF (32*MB_STRIDE)
#define MOE_STAGE (MA_BUF + 2*MB_BUF)
#define MOE_SMEM (2*MOE_STAGE*4)

__global__ void __launch_bounds__(256, 2) moe13_gemm(
    const float* __restrict__ W1, const float* __restrict__ W3)
{
    extern __shared__ float dsm[];
    int e = blockIdx.z;
    int cnt = g_counts[e], off = g_offsets[e];
    int bm = blockIdx.y * 128;
    if (bm >= cnt) return;
    int bn = blockIdx.x * 64;
    int tid = threadIdx.x;
    int lane = tid & 31, wid = tid >> 5;
    int warp_m = wid >> 1, warp_n = wid & 1;
    int lq = lane >> 2, lr = lane & 3;

    const float* W1e = W1 + (size_t)e*Dm*NI;
    const float* W3e = W3 + (size_t)e*Dm*NI;

    const float* aptr[4];
    #pragma unroll
    for (int r = 0; r < 4; r++) {
        int row = bm + r*32 + (tid >> 3);
        int re = row < cnt ? row : cnt - 1;
        aptr[r] = g_h + (size_t)g_slot_token[off + re] * Dm;
    }
    int ak4 = (tid & 7) * 4;
    int brow = tid >> 4;
    int bc4  = (tid & 15) * 4;
    const float* b1src = W1e + (size_t)brow*NI + bn + bc4;
    const float* b3src = W3e + (size_t)brow*NI + bn + bc4;

    unsigned sm0 = (unsigned)__cvta_generic_to_shared(dsm);
    unsigned a_dst0  = sm0 + (((tid>>3)*MA_STRIDE) + ak4)*4u;
    unsigned b1_dst0 = sm0 + (unsigned)(MA_BUF + brow*MB_STRIDE + bc4)*4u;
    unsigned b3_dst0 = b1_dst0 + (unsigned)(MB_BUF)*4u;

    float acc1[2][4][4], acc3[2][4][4];
    #pragma unroll
    for (int i=0;i<2;i++)
        #pragma unroll
        for(int j=0;j<4;j++)
            #pragma unroll
            for(int c=0;c<4;c++){acc1[i][j][c]=0.f;acc3[i][j][c]=0.f;}

    const int nkt = Dm >> 5;
    #pragma unroll
    for (int r = 0; r < 4; r++)
        cp16(a_dst0 + (unsigned)(r*32*MA_STRIDE)*4u, aptr[r] + ak4);
    #pragma unroll
    for (int r = 0; r < 2; r++) {
        cp16(b1_dst0 + (unsigned)(r*16*MB_STRIDE)*4u, b1src + (size_t)(r*16)*NI);
        cp16(b3_dst0 + (unsigned)(r*16*MB_STRIDE)*4u, b3src + (size_t)(r*16)*NI);
    }
    cp_commit();

    for (int it = 0; it < nkt; it++) {
        int cur = it & 1;
        if (it + 1 < nkt) {
            int nb = (it + 1) & 1;
            int k0 = (it + 1) << 5;
            unsigned ad  = a_dst0  + (unsigned)(nb*MOE_STAGE)*4u;
            unsigned b1d = b1_dst0 + (unsigned)(nb*MOE_STAGE)*4u;
            unsigned b3d = b3_dst0 + (unsigned)(nb*MOE_STAGE)*4u;
            #pragma unroll
            for (int r = 0; r < 4; r++)
                cp16(ad + (unsigned)(r*32*MA_STRIDE)*4u, aptr[r] + k0 + ak4);
            #pragma unroll
            for (int r = 0; r < 2; r++) {
                cp16(b1d + (unsigned)(r*16*MB_STRIDE)*4u, b1src + (size_t)(k0 + r*16)*NI);
                cp16(b3d + (unsigned)(r*16*MB_STRIDE)*4u, b3src + (size_t)(k0 + r*16)*NI);
            }
            cp_commit();
            cp_wait<1>();
        } else {
            cp_wait<0>();
        }
        __syncthreads();
        const float* Ac  = dsm + cur*MOE_STAGE;
        const float* B1c = Ac + MA_BUF;
        const float* B3c = B1c + MB_BUF;
        #pragma unroll
        for (int ks = 0; ks < 4; ks++) {
            int k8 = ks*8;
            unsigned af[2][4], b1f[4][2], b3f[4][2];
            #pragma unroll
            for (int mt=0; mt<2; mt++) {
                int m0 = warp_m*32 + mt*16;
                const float* p = &Ac[(m0+lq)*MA_STRIDE + k8 + lr];
                af[mt][0] = __float_as_uint(p[0]);
                af[mt][1] = __float_as_uint(p[8*MA_STRIDE]);
                af[mt][2] = __float_as_uint(p[4]);
                af[mt][3] = __float_as_uint(p[8*MA_STRIDE+4]);
            }
            #pragma unroll
            for (int nt=0; nt<4; nt++) {
                int n0 = warp_n*32 + nt*8 + lq;
                b1f[nt][0] = __float_as_uint(B1c[(k8+lr)*MB_STRIDE + n0]);
                b1f[nt][1] = __float_as_uint(B1c[(k8+4+lr)*MB_STRIDE + n0]);
                b3f[nt][0] = __float_as_uint(B3c[(k8+lr)*MB_STRIDE + n0]);
                b3f[nt][1] = __float_as_uint(B3c[(k8+4+lr)*MB_STRIDE + n0]);
            }
            #pragma unroll
            for (int mt=0; mt<2; mt++)
                #pragma unroll
                for (int nt=0; nt<4; nt++) {
                    MMA_TF32(acc1[mt][nt][0], acc1[mt][nt][1], acc1[mt][nt][2], acc1[mt][nt][3],
                             af[mt][0], af[mt][1], af[mt][2], af[mt][3],
                             b1f[nt][0], b1f[nt][1]);
                    MMA_TF32(acc3[mt][nt][0], acc3[mt][nt][1], acc3[mt][nt][2], acc3[mt][nt][3],
                             af[mt][0], af[mt][1], af[mt][2], af[mt][3],
                             b3f[nt][0], b3f[nt][1]);
                }
        }
        __syncthreads();
    }
    #pragma unroll
    for (int mt=0; mt<2; mt++) {
        int row0 = bm + warp_m*32 + mt*16 + lq;
        #pragma unroll
        for (int half=0; half<2; half++) {
            int row = row0 + half*8;
            if (row >= cnt) continue;
            size_t crow = (size_t)(off + row);
            #pragma unroll
            for (int nt=0; nt<4; nt++) {
                int col = bn + warp_n*32 + nt*8 + 2*lr;
                float gg0 = acc1[mt][nt][half*2+0], uu0 = acc3[mt][nt][half*2+0];
                float gg1 = acc1[mt][nt][half*2+1], uu1 = acc3[mt][nt][half*2+1];
                float2 v;
                v.x = f2tff(gg0 / (1.f + __expf(-gg0)) * uu0);
                v.y = f2tff(gg1 / (1.f + __expf(-gg1)) * uu1);
                *(float2*)(g_g + crow*NI + col) = v;
            }
        }
    }
}

// ---------------- RoPE (rounds q,k; also rounds v) ----------------
__global__ void rope_kernel() {
    int idx = blockIdx.x*256 + threadIdx.x;
    const int totq = Ttok*NH*(HDv/2);
    const int totk = totq + Ttok*KVHv*(HDv/2);
    const int tot  = totk + Ttok*(KVD/2);
    if (idx >= tot) return;
    if (idx >= totk) {
        int id2 = idx - totk;
        float* p = g_v + (size_t)id2*2;
        p[0] = f2tff(p[0]); p[1] = f2tff(p[1]);
        return;
    }
    float* base; int t, i;
    if (idx < totq) {
        i = idx & 63;
        int hh = (idx >> 6) & (NH-1);
        t = idx >> 10;
        base = g_q + (size_t)t*Dm + hh*HDv + 2*i;
    } else {
        int id2 = idx - totq;
        i = id2 & 63;
        int hh = (id2 >> 6) & (KVHv-1);
        t = id2 >> 8;
        base = g_k + (size_t)t*KVD + hh*HDv + 2*i;
    }
    int pos = t & (Lq-1);
    float inv = exp2f(-(float)i * (13.287712379549449f/64.f));
    float ang = (float)pos * inv;
    float c = cosf(ang), s = sinf(ang);
    float xr = base[0], xi = base[1];
    base[0] = f2tff(xr*c - xi*s);
    base[1] = f2tff(xr*s + xi*c);
}

// ---------------- tensor-core flash attention: 128-row Q blocks, 8 warps ----------------
#define QPAD 132
#define VPAD 136
#define PPAD 36
#define AT_KS 0
#define AT_KBUF (32*QPAD)                     /* 4224 */
#define AT_VS (2*AT_KBUF)                     /* 8448 */
#define AT_VBUF (32*VPAD)                     /* 4352 */
#define AT_QP (AT_VS + 2*AT_VBUF)             /* 17152: Q staging (128*132), reused for P (128*36) */
#define AT_SMEM_WORDS (AT_QP + 128*QPAD)      /* 34048 -> 136192 B, 1 CTA/SM */

__global__ void __launch_bounds__(256, 1) attn_mma_kernel() {
    extern __shared__ float sm[];
    int b = blockIdx.z, h = blockIdx.y;
    int q0 = blockIdx.x * 128;
    int kvh = h >> 2;
    int tid = threadIdx.x;
    int lane = tid & 31, w = tid >> 5;      // 8 warps, 16 q-rows each
    int lq = lane >> 2, lr = lane & 3;
    const float scale = 0.08838834764831845f;

    unsigned sm_base = (unsigned)__cvta_generic_to_shared(sm);

    // prologue: cp.async K/V tile 0 -> buf 0
    for (int idx = tid; idx < 32*32; idx += 256) {
        int row = idx >> 5, c4 = (idx & 31) * 4;
        size_t goff = (size_t)(b*Lq + row)*KVD + kvh*HDv + c4;
        cp16(sm_base + (unsigned)(AT_KS + row*QPAD + c4)*4u, g_k + goff);
        cp16(sm_base + (unsigned)(AT_VS + row*VPAD + c4)*4u, g_v + goff);
    }
    cp_commit();

    // stage Q tile (128x128) into smem, then lift to per-warp register fragments
    for (int idx = tid; idx < 128*32; idx += 256) {
        int row = idx >> 5, c4 = (idx & 31) * 4;
        float4 qv = *(const float4*)(g_q + (size_t)(b*Lq + q0 + row)*Dm + h*HDv + c4);
        *(float4*)&sm[AT_QP + row*QPAD + c4] = qv;
    }
    __syncthreads();
    unsigned qf[16][4];
    #pragma unroll
    for (int ks = 0; ks < 16; ks++) {
        int k8 = ks*8;
        const float* qp = &sm[AT_QP + (w*16+lq)*QPAD + k8 + lr];
        qf[ks][0] = __float_as_uint(qp[0]);
        qf[ks][1] = __float_as_uint(qp[8*QPAD]);
        qf[ks][2] = __float_as_uint(qp[4]);
        qf[ks][3] = __float_as_uint(qp[8*QPAD+4]);
    }
    // Q staging region is reused for P; first-loop __syncthreads orders reads before writes.

    float o[16][4];
    #pragma unroll
    for (int nt=0;nt<16;nt++){o[nt][0]=0.f;o[nt][1]=0.f;o[nt][2]=0.f;o[nt][3]=0.f;}
    float m0 = -1e30f, m1 = -1e30f, l0 = 0.f, l1 = 0.f;
    int row_base = q0 + w*16;
    int ntiles = (q0 + 128) / 32;

    for (int kt = 0; kt < ntiles; kt++) {
        int cur = kt & 1;
        if (kt + 1 < ntiles) {
            int nb = (kt + 1) & 1;
            int nbase = (kt + 1) * 32;
            for (int idx = tid; idx < 32*32; idx += 256) {
                int row = idx >> 5, c4 = (idx & 31) * 4;
                size_t goff = (size_t)(b*Lq + nbase + row)*KVD + kvh*HDv + c4;
                cp16(sm_base + (unsigned)(AT_KS + nb*AT_KBUF + row*QPAD + c4)*4u, g_k + goff);
                cp16(sm_base + (unsigned)(AT_VS + nb*AT_VBUF + row*VPAD + c4)*4u, g_v + goff);
            }
            cp_commit();
            cp_wait<1>();
        } else {
            cp_wait<0>();
        }
        __syncthreads();
        int base = kt * 32;
        const float* Kc = sm + AT_KS + cur*AT_KBUF;
        const float* Vc = sm + AT_VS + cur*AT_VBUF;

        // skip tiles entirely above this warp's diagonal (bit-identical state)
        if (base <= row_base + 15) {
            float s[4][4];
            #pragma unroll
            for (int nt=0;nt<4;nt++){s[nt][0]=0.f;s[nt][1]=0.f;s[nt][2]=0.f;s[nt][3]=0.f;}
            #pragma unroll
            for (int ks = 0; ks < 16; ks++) {
                int k8 = ks*8;
                #pragma unroll
                for (int nt=0; nt<4; nt++) {
                    unsigned b0 = __float_as_uint(Kc[(nt*8+lq)*QPAD + k8 + lr]);
                    unsigned b1 = __float_as_uint(Kc[(nt*8+lq)*QPAD + k8 + lr + 4]);
                    MMA_TF32(s[nt][0], s[nt][1], s[nt][2], s[nt][3],
                             qf[ks][0], qf[ks][1], qf[ks][2], qf[ks][3], b0, b1);
                }
            }
            #pragma unroll
            for (int nt=0; nt<4; nt++) {
                s[nt][0]*=scale; s[nt][1]*=scale; s[nt][2]*=scale; s[nt][3]*=scale;
            }

            if (base + 31 > row_base) {
                int i0 = row_base + lq, i1 = row_base + lq + 8;
                #pragma unroll
                for (int nt=0; nt<4; nt++) {
                    int j = base + nt*8 + 2*lr;
                    if (j   > i0) s[nt][0] = -1e30f;
                    if (j+1 > i0) s[nt][1] = -1e30f;
                    if (j   > i1) s[nt][2] = -1e30f;
                    if (j+1 > i1) s[nt][3] = -1e30f;
                }
            }

            float mx0 = -1e30f, mx1 = -1e30f;
            #pragma unroll
            for (int nt=0; nt<4; nt++) {
                mx0 = fmaxf(mx0, fmaxf(s[nt][0], s[nt][1]));
                mx1 = fmaxf(mx1, fmaxf(s[nt][2], s[nt][3]));
            }
            mx0 = fmaxf(mx0, __shfl_xor_sync(0xffffffffu, mx0, 1));
            mx0 = fmaxf(mx0, __shfl_xor_sync(0xffffffffu, mx0, 2));
            mx1 = fmaxf(mx1, __shfl_xor_sync(0xffffffffu, mx1, 1));
            mx1 = fmaxf(mx1, __shfl_xor_sync(0xffffffffu, mx1, 2));
            float mn0 = fmaxf(m0, mx0), mn1 = fmaxf(m1, mx1);
            float al0 = __expf(m0 - mn0), al1 = __expf(m1 - mn1);
            float rs0 = 0.f, rs1 = 0.f;
            #pragma unroll
            for (int nt=0; nt<4; nt++) {
                s[nt][0] = __expf(s[nt][0] - mn0);
                s[nt][1] = __expf(s[nt][1] - mn0);
                s[nt][2] = __expf(s[nt][2] - mn1);
                s[nt][3] = __expf(s[nt][3] - mn1);
                rs0 += s[nt][0] + s[nt][1];
                rs1 += s[nt][2] + s[nt][3];
            }
            rs0 += __shfl_xor_sync(0xffffffffu, rs0, 1);
            rs0 += __shfl_xor_sync(0xffffffffu, rs0, 2);
            rs1 += __shfl_xor_sync(0xffffffffu, rs1, 1);
            rs1 += __shfl_xor_sync(0xffffffffu, rs1, 2);
            l0 = l0*al0 + rs0;
            l1 = l1*al1 + rs1;
            m0 = mn0; m1 = mn1;
            #pragma unroll
            for (int nt=0; nt<16; nt++) {
                o[nt][0]*=al0; o[nt][1]*=al0; o[nt][2]*=al1; o[nt][3]*=al1;
            }

            // stage P (tf32) into per-warp smem rows (Q staging region, stride PPAD)
            #pragma unroll
            for (int nt=0; nt<4; nt++) {
                float* p0 = &sm[AT_QP + (w*16+lq)*PPAD + nt*8 + 2*lr];
                p0[0] = __uint_as_float(f2tf(s[nt][0]));
                p0[1] = __uint_as_float(f2tf(s[nt][1]));
                float* p1 = &sm[AT_QP + (w*16+lq+8)*PPAD + nt*8 + 2*lr];
                p1[0] = __uint_as_float(f2tf(s[nt][2]));
                p1[1] = __uint_as_float(f2tf(s[nt][3]));
            }
            __syncwarp();

            #pragma unroll
            for (int ks = 0; ks < 4; ks++) {
                int k8 = ks*8;
                const float* pp = &sm[AT_QP + (w*16+lq)*PPAD + k8 + lr];
                unsigned a0 = __float_as_uint(pp[0]);
                unsigned a1 = __float_as_uint(pp[8*PPAD]);
                unsigned a2 = __float_as_uint(pp[4]);
                unsigned a3 = __float_as_uint(pp[8*PPAD+4]);
                #pragma unroll
                for (int nt=0; nt<16; nt++) {
                    unsigned b0 = __float_as_uint(Vc[(k8+lr)*VPAD + nt*8 + lq]);
                    unsigned b1 = __float_as_uint(Vc[(k8+lr+4)*VPAD + nt*8 + lq]);
                    MMA_TF32(o[nt][0], o[nt][1], o[nt][2], o[nt][3],
                             a0, a1, a2, a3, b0, b1);
                }
            }
        }
        __syncthreads();
    }

    float inv0 = 1.f / l0, inv1 = 1.f / l1;
    int t0 = b*Lq + row_base + lq;
    #pragma unroll
    for (int nt=0; nt<16; nt++) {
        int col = h*HDv + nt*8 + 2*lr;
        float2 v0 = make_float2(f2tff(o[nt][0]*inv0), f2tff(o[nt][1]*inv0));
        float2 v1 = make_float2(f2tff(o[nt][2]*inv1), f2tff(o[nt][3]*inv1));
        *(float2*)(g_ao + (size_t)t0*Dm + col) = v0;
        *(float2*)(g_ao + (size_t)(t0+8)*Dm + col) = v1;
    }
}

// ---------------- gating ----------------
__global__ void gate_kernel(const float* __restrict__ gw) {
    int t = blockIdx.x;
    int warp = threadIdx.x >> 5, lane = threadIdx.x & 31;
    const float* row = g_h + (size_t)t*Dm;
    float s = 0.f;
    for (int i = lane; i < Dm; i += 32) s += row[i] * gw[(size_t)i*NE + warp];
    for (int o = 16; o; o >>= 1) s += __shfl_xor_sync(0xffffffffu, s, o);
    __shared__ float logits[NE];
    if (lane == 0) logits[warp] = s;
    __syncthreads();
    if (threadIdx.x == 0) {
        float mx = logits[0];
        for (int e = 1; e < NE; e++) mx = fmaxf(mx, logits[e]);
        float ex[NE]; float sum = 0.f;
        for (int e = 0; e < NE; e++) { ex[e] = expf(logits[e]-mx); sum += ex[e]; }
        float invs = 1.f/sum;
        float sc[NE];
        for (int e = 0; e < NE; e++) { sc[e] = ex[e]*invs; g_scores[t*NE+e] = sc[e]; }
        int e0 = 0; float m0 = sc[0];
        for (int e = 1; e < NE; e++) if (sc[e] > m0) { m0 = sc[e]; e0 = e; }
        int e1 = -1; float m1 = -1.f;
        for (int e = 0; e < NE; e++) if (e != e0 && sc[e] > m1) { m1 = sc[e]; e1 = e; }
        float wsum = m0 + m1;
        g_top_idx[t*2]   = e0;  g_top_idx[t*2+1] = e1;
        g_top_w[t*2]     = m0/wsum;
        g_top_w[t*2+1]   = m1/wsum;
        atomicAdd(&g_counts[e0], 1);
        atomicAdd(&g_counts[e1], 1);
    }
}

// fused finalize (aux loss + offsets) + scatter (slot assignment)
__global__ void finalize_scatter_kernel(float* aux_out) {
    int warp = threadIdx.x >> 5, lane = threadIdx.x & 31;
    float s = 0.f;
    for (int t = lane; t < Ttok; t += 32) s += g_scores[t*NE + warp];
    for (int o = 16; o; o >>= 1) s += __shfl_xor_sync(0xffffffffu, s, o);
    __shared__ float ps[NE];
    if (lane == 0) ps[warp] = s;
    __syncthreads();
    if (threadIdx.x == 0) {
        int off = 0; float aux = 0.f;
        for (int e = 0; e < NE; e++) {
            g_offsets[e] = off; off += g_counts[e];
            float f = (float)g_counts[e] / (float)Ttok;
            float p = ps[e] / (float)Ttok;
            aux += f * p;
        }
        g_offsets[NE] = off;
        aux_out[0] = 0.01f * (float)NE * aux;
    }
    __syncthreads();
    for (int t = threadIdx.x; t < Ttok; t += 256) {
        #pragma unroll
        for (int j = 0; j < 2; j++) {
            int e = g_top_idx[t*2+j];
            int pos = atomicAdd(&g_cursor[e], 1);
            int slot = g_offsets[e] + pos;
            g_slot_token[slot] = t;
            g_slot_w[slot] = g_top_w[t*2+j];
            g_slot_of[t*2+j] = slot;
        }
    }
}

__global__ void final_add_kernel(float* __restrict__ out) {
    int t = blockIdx.x;
    int s0 = g_slot_of[t*2], s1 = g_slot_of[t*2+1];
    float w0 = g_slot_w[s0], w1 = g_slot_w[s1];
    for (int i = threadIdx.x*4; i < Dm; i += 256*4) {
        float4 a  = *(float4*)(out + (size_t)t*Dm + i);
        float4 y0 = *(const float4*)(g_y + (size_t)s0*Dm + i);
        float4 y1 = *(const float4*)(g_y + (size_t)s1*Dm + i);
        a.x += w0*y0.x + w1*y1.x;
        a.y += w0*y0.y + w1*y1.y;
        a.z += w0*y0.z + w1*y1.z;
        a.w += w0*y0.w + w1*y1.w;
        *(float4*)(out + (size_t)t*Dm + i) = a;
    }
}

// ---------------- launch ----------------
extern "C" void kernel_launch(void* const* d_in, const int* in_sizes, int n_in,
                              void* d_out, int out_size) {
    const float* x           = (const float*)d_in[0];
    const float* w_q         = (const float*)d_in[1];
    const float* w_k         = (const float*)d_in[2];
    const float* w_v         = (const float*)d_in[3];
    const float* w_o         = (const float*)d_in[4];
    const float* attn_norm_w = (const float*)d_in[5];
    const float* moe_norm_w  = (const float*)d_in[6];
    const float* gate_w      = (const float*)d_in[7];
    const float* w1          = (const float*)d_in[8];
    const float* w3          = (const float*)d_in[9];
    const float* w2          = (const float*)d_in[10];
    float* out = (float*)d_out;

    float *ph, *pq, *pk, *pv, *pao, *pg, *py;
    float *pwq, *pwk, *pwv, *pwo;
    cudaGetSymbolAddress((void**)&ph,  g_h);
    cudaGetSymbolAddress((void**)&pq,  g_q);
    cudaGetSymbolAddress((void**)&pk,  g_k);
    cudaGetSymbolAddress((void**)&pv,  g_v);
    cudaGetSymbolAddress((void**)&pao, g_ao);
    cudaGetSymbolAddress((void**)&pg,  g_g);
    cudaGetSymbolAddress((void**)&py,  g_y);
    cudaGetSymbolAddress((void**)&pwq, r_wq);
    cudaGetSymbolAddress((void**)&pwk, r_wk);
    cudaGetSymbolAddress((void**)&pwv, r_wv);
    cudaGetSymbolAddress((void**)&pwo, r_wo);

    static int attr_set = 0;
    const int attn_smem = AT_SMEM_WORDS * 4;
    if (!attr_set) {
        cudaFuncSetAttribute(attn_mma_kernel,
                             cudaFuncAttributeMaxDynamicSharedMemorySize, attn_smem);
        cudaFuncSetAttribute(tf32_gemm,
                             cudaFuncAttributeMaxDynamicSharedMemorySize, GEMM_SMEM);
        cudaFuncSetAttribute(moe13_gemm,
                             cudaFuncAttributeMaxDynamicSharedMemorySize, MOE_SMEM);
        attr_set = 1;
    }

    prep_kernel<<<PREP_TOTAL/256, 256>>>(w_q, w_k, w_v, w_o, pwq, pwk, pwv, pwo);

    rmsnorm_kernel<<<Ttok, 256>>>(x, attn_norm_w, ph);
    tf32_gemm<<<dim3(Dm/128, Ttok/128, 1), 256, GEMM_SMEM>>>(ph, pwq, pq, Ttok, Dm, Dm,
                                                  nullptr, 0, nullptr, nullptr);
    tf32_gemm<<<dim3(KVD/128, Ttok/128, 2), 256, GEMM_SMEM>>>(ph, pwk, pk, Ttok, KVD, Dm,
                                                   nullptr, 0, pwv, pv);
    {
        int tot = Ttok*NH*(HDv/2) + Ttok*KVHv*(HDv/2) + Ttok*(KVD/2);
        rope_kernel<<<(tot + 255)/256, 256>>>();
    }
    attn_mma_kernel<<<dim3(Lq/128, NH, Bq), 256, attn_smem>>>();
    tf32_gemm<<<dim3(Dm/128, Ttok/128, 1), 256, GEMM_SMEM>>>(pao, pwo, out, Ttok, Dm, Dm,
                                                  x, 0, nullptr, nullptr);
    rmsnorm_kernel<<<Ttok, 256>>>(out, moe_norm_w, ph);
    gate_kernel<<<Ttok, 256>>>(gate_w);
    finalize_scatter_kernel<<<1, 256>>>(out + (size_t)Ttok*Dm);
    moe13_gemm<<<dim3(NI/64, SLOTS/128, NE), 256, MOE_SMEM>>>(w1, w3);
    tf32_gemm<<<dim3(Dm/128, SLOTS/128, NE), 256, GEMM_SMEM>>>(pg, w2, py, 0, Dm, NI,
                                                    nullptr, 2, nullptr, nullptr);
    final_add_kernel<<<Ttok, 256>>>(out);
}

// round 14
// speedup vs baseline: 1.0205x; 1.0205x over previous
#include <cuda_runtime.h>
#include <math.h>

#define Bq 2
#define Lq 2048
#define Dm 2048
#define NH 16
#define HDv 128
#define KVHv 4
#define NE 8
#define NI 1024
#define Ttok (Bq*Lq)          /* 4096 */
#define KVD (KVHv*HDv)        /* 512  */
#define SLOTS (Ttok*2)        /* 8192 */

// ---------------- scratch ----------------
__device__ float g_h[Ttok*Dm];
__device__ float g_q[Ttok*Dm];
__device__ float g_k[Ttok*KVD];
__device__ float g_v[Ttok*KVD];
__device__ float g_ao[Ttok*Dm];
__device__ float g_g[SLOTS*NI];
__device__ float g_y[SLOTS*Dm];
__device__ float g_scores[Ttok*NE];
__device__ int   g_counts[NE];
__device__ int   g_offsets[NE+1];
__device__ int   g_cursor[NE];
__device__ int   g_top_idx[Ttok*2];
__device__ float g_top_w[Ttok*2];
__device__ int   g_slot_token[SLOTS];
__device__ float g_slot_w[SLOTS];
__device__ int   g_slot_of[Ttok*2];
__device__ float r_wq[Dm*Dm];
__device__ float r_wk[Dm*KVD];
__device__ float r_wv[Dm*KVD];
__device__ float r_wo[Dm*Dm];

__device__ __forceinline__ unsigned f2tf(float x) {
    unsigned r; asm("cvt.rna.tf32.f32 %0, %1;" : "=r"(r) : "f"(x)); return r;
}
__device__ __forceinline__ float f2tff(float x) { return __uint_as_float(f2tf(x)); }
__device__ __forceinline__ void cp16(unsigned d, const void* s) {
    asm volatile("cp.async.cg.shared.global [%0], [%1], 16;" :: "r"(d), "l"(s));
}
__device__ __forceinline__ void cp_commit() {
    asm volatile("cp.async.commit_group;");
}
template<int N> __device__ __forceinline__ void cp_wait() {
    asm volatile("cp.async.wait_group %0;" :: "n"(N));
}
#define MMA_TF32(d0,d1,d2,d3,a0,a1,a2,a3,b0,b1) \
    asm volatile( \
        "mma.sync.aligned.m16n8k8.row.col.f32.tf32.tf32.f32 " \
        "{%0,%1,%2,%3}, {%4,%5,%6,%7}, {%8,%9}, {%0,%1,%2,%3};" \
        : "+f"(d0), "+f"(d1), "+f"(d2), "+f"(d3) \
        : "r"(a0), "r"(a1), "r"(a2), "r"(a3), "r"(b0), "r"(b1))

// ---------------- small kernels ----------------
__global__ void zero_kernel() {
    int i = threadIdx.x;
    if (i < NE) { g_counts[i] = 0; g_cursor[i] = 0; }
}

__global__ void roundcopy(const float* __restrict__ s, float* __restrict__ d, int n4) {
    int i = blockIdx.x*256 + threadIdx.x;
    if (i >= n4) return;
    float4 v = ((const float4*)s)[i];
    uint4 u;
    u.x = f2tf(v.x); u.y = f2tf(v.y); u.z = f2tf(v.z); u.w = f2tf(v.w);
    ((uint4*)d)[i] = u;
}

__global__ void rmsnorm_kernel(const float* __restrict__ in,
                               const float* __restrict__ w,
                               float* __restrict__ out) {
    int t = blockIdx.x;
    const float* row = in + (size_t)t*Dm;
    float ss = 0.f;
    for (int i = threadIdx.x; i < Dm; i += 256) { float v = row[i]; ss += v*v; }
    __shared__ float red[8];
    for (int o = 16; o; o >>= 1) ss += __shfl_xor_sync(0xffffffffu, ss, o);
    if ((threadIdx.x & 31) == 0) red[threadIdx.x >> 5] = ss;
    __syncthreads();
    float tot = 0.f;
    #pragma unroll
    for (int i = 0; i < 8; i++) tot += red[i];
    float inv = rsqrtf(tot * (1.f/(float)Dm) + 1e-5f);
    for (int i = threadIdx.x; i < Dm; i += 256)
        out[(size_t)t*Dm + i] = f2tff(row[i] * inv * w[i]);
}

// ---------------- tf32 GEMM, cp.async double-buffered (2-stage) ----------------
#define GA_STRIDE 36
#define GB_STRIDE 136
#define GA_BUF (128*GA_STRIDE)
#define GB_BUF (32*GB_STRIDE)
#define GEMM_SMEM ((2*GA_BUF + 2*GB_BUF)*4)

__global__ void __launch_bounds__(256, 2) tf32_gemm(
    const float* __restrict__ A, const float* __restrict__ B,
    float* __restrict__ C, int M, int N, int K,
    const float* __restrict__ addsrc, int mode,
    const float* __restrict__ B2, float* __restrict__ C2)
{
    extern __shared__ float dsm[];
    float* As = dsm;
    float* Bs = dsm + 2*GA_BUF;
    int cnt, off;
    if (mode == 0) {
        cnt = M; off = 0;
        if (blockIdx.z == 1) { B = B2; C = C2; }
    } else {
        int e = blockIdx.z;
        cnt = g_counts[e]; off = g_offsets[e];
        B += (size_t)e * K * N;
    }
    int bm = blockIdx.y * 128;
    if (bm >= cnt) return;
    int bn = blockIdx.x * 128;
    int tid = threadIdx.x;
    int lane = tid & 31, wid = tid >> 5;
    int warp_m = wid >> 2, warp_n = wid & 3;
    int lq = lane >> 2, lr = lane & 3;

    const float* aptr[4];
    #pragma unroll
    for (int r = 0; r < 4; r++) {
        int row = bm + r*32 + (tid >> 3);
        int re = row < cnt ? row : cnt - 1;
        if (mode == 1)      aptr[r] = g_h + (size_t)g_slot_token[off + re] * K;
        else if (mode == 2) aptr[r] = A + (size_t)(off + re) * K;
        else                aptr[r] = A + (size_t)re * K;
    }
    int ak4 = (tid & 7) * 4;
    int bk  = tid >> 5;
    int bn4 = lane * 4;
    const float* bsrc = B + (size_t)bk*N + bn + bn4;

    unsigned as_sm = (unsigned)__cvta_generic_to_shared(As);
    unsigned bs_sm = (unsigned)__cvta_generic_to_shared(Bs);
    unsigned a_dst0 = as_sm + (((tid>>3)*GA_STRIDE) + ak4)*4u;
    unsigned b_dst0 = bs_sm + ((bk*GB_STRIDE) + bn4)*4u;

    float acc[4][4][4];
    #pragma unroll
    for (int i=0;i<4;i++)
        #pragma unroll
        for(int j=0;j<4;j++)
            #pragma unroll
            for(int c=0;c<4;c++) acc[i][j][c]=0.f;

    int nkt = K >> 5;
    #pragma unroll
    for (int r = 0; r < 4; r++)
        cp16(a_dst0 + (unsigned)(r*32*GA_STRIDE)*4u, aptr[r] + ak4);
    #pragma unroll
    for (int r = 0; r < 4; r++)
        cp16(b_dst0 + (unsigned)(r*8*GB_STRIDE)*4u, bsrc + (size_t)(r*8)*N);
    cp_commit();

    for (int it = 0; it < nkt; it++) {
        int cur = it & 1;
        if (it + 1 < nkt) {
            int nb = (it + 1) & 1;
            int k0 = (it + 1) << 5;
            unsigned ad = a_dst0 + (unsigned)(nb*GA_BUF)*4u;
            unsigned bd = b_dst0 + (unsigned)(nb*GB_BUF)*4u;
            #pragma unroll
            for (int r = 0; r < 4; r++)
                cp16(ad + (unsigned)(r*32*GA_STRIDE)*4u, aptr[r] + k0 + ak4);
            #pragma unroll
            for (int r = 0; r < 4; r++)
                cp16(bd + (unsigned)(r*8*GB_STRIDE)*4u, bsrc + (size_t)(k0 + r*8)*N);
            cp_commit();
            cp_wait<1>();
        } else {
            cp_wait<0>();
        }
        __syncthreads();
        const float* Ac = As + cur*GA_BUF;
        const float* Bc = Bs + cur*GB_BUF;
        #pragma unroll
        for (int ks = 0; ks < 4; ks++) {
            int k8 = ks*8;
            unsigned af[4][4], bf[4][2];
            #pragma unroll
            for (int mt=0; mt<4; mt++) {
                int m0 = warp_m*64 + mt*16;
                const float* p = &Ac[(m0+lq)*GA_STRIDE + k8 + lr];
                af[mt][0] = __float_as_uint(p[0]);
                af[mt][1] = __float_as_uint(p[8*GA_STRIDE]);
                af[mt][2] = __float_as_uint(p[4]);
                af[mt][3] = __float_as_uint(p[8*GA_STRIDE+4]);
            }
            #pragma unroll
            for (int nt=0; nt<4; nt++) {
                int n0 = warp_n*32 + nt*8 + lq;
                bf[nt][0] = __float_as_uint(Bc[(k8+lr)*GB_STRIDE + n0]);
                bf[nt][1] = __float_as_uint(Bc[(k8+4+lr)*GB_STRIDE + n0]);
            }
            #pragma unroll
            for (int mt=0; mt<4; mt++)
                #pragma unroll
                for (int nt=0; nt<4; nt++)
                    MMA_TF32(acc[mt][nt][0], acc[mt][nt][1], acc[mt][nt][2], acc[mt][nt][3],
                             af[mt][0], af[mt][1], af[mt][2], af[mt][3],
                             bf[nt][0], bf[nt][1]);
        }
        __syncthreads();
    }
    #pragma unroll
    for (int mt=0; mt<4; mt++) {
        int row0 = bm + warp_m*64 + mt*16 + lq;
        #pragma unroll
        for (int half=0; half<2; half++) {
            int row = row0 + half*8;
            if (row >= cnt) continue;
            size_t crow = (size_t)(off + row);
            #pragma unroll
            for (int nt=0; nt<4; nt++) {
                int col = bn + warp_n*32 + nt*8 + 2*lr;
                float2 v;
                v.x = acc[mt][nt][half*2+0];
                v.y = acc[mt][nt][half*2+1];
                if (addsrc) {
                    float2 s = *(const float2*)(addsrc + crow*N + col);
                    v.x += s.x; v.y += s.y;
                }
                *(float2*)(C + crow*N + col) = v;
            }
        }
    }
}

// ---------------- fused MoE up-proj: g_g = silu(Xg@W1) * (Xg@W3) ----------------
#define MA_STRIDE 36
#define MB_STRIDE 72
#define MA_BUF (128*MA_STRIDE)
#define MB_BUF (32*MB_STRIDE)
#define MOE_STAGE (MA_BUF + 2*MB_BUF)
#define MOE_SMEM (2*MOE_STAGE*4)

__global__ void __launch_bounds__(256, 2) moe13_gemm(
    const float* __restrict__ W1, const float* __restrict__ W3)
{
    extern __shared__ float dsm[];
    int e = blockIdx.z;
    int cnt = g_counts[e], off = g_offsets[e];
    int bm = blockIdx.y * 128;
    if (bm >= cnt) return;
    int bn = blockIdx.x * 64;
    int tid = threadIdx.x;
    int lane = tid & 31, wid = tid >> 5;
    int warp_m = wid >> 1, warp_n = wid & 1;
    int lq = lane >> 2, lr = lane & 3;

    const float* W1e = W1 + (size_t)e*Dm*NI;
    const float* W3e = W3 + (size_t)e*Dm*NI;

    const float* aptr[4];
    #pragma unroll
    for (int r = 0; r < 4; r++) {
        int row = bm + r*32 + (tid >> 3);
        int re = row < cnt ? row : cnt - 1;
        aptr[r] = g_h + (size_t)g_slot_token[off + re] * Dm;
    }
    int ak4 = (tid & 7) * 4;
    int brow = tid >> 4;
    int bc4  = (tid & 15) * 4;
    const float* b1src = W1e + (size_t)brow*NI + bn + bc4;
    const float* b3src = W3e + (size_t)brow*NI + bn + bc4;

    unsigned sm0 = (unsigned)__cvta_generic_to_shared(dsm);
    unsigned a_dst0  = sm0 + (((tid>>3)*MA_STRIDE) + ak4)*4u;
    unsigned b1_dst0 = sm0 + (unsigned)(MA_BUF + brow*MB_STRIDE + bc4)*4u;
    unsigned b3_dst0 = b1_dst0 + (unsigned)(MB_BUF)*4u;

    float acc1[2][4][4], acc3[2][4][4];
    #pragma unroll
    for (int i=0;i<2;i++)
        #pragma unroll
        for(int j=0;j<4;j++)
            #pragma unroll
            for(int c=0;c<4;c++){acc1[i][j][c]=0.f;acc3[i][j][c]=0.f;}

    const int nkt = Dm >> 5;
    #pragma unroll
    for (int r = 0; r < 4; r++)
        cp16(a_dst0 + (unsigned)(r*32*MA_STRIDE)*4u, aptr[r] + ak4);
    #pragma unroll
    for (int r = 0; r < 2; r++) {
        cp16(b1_dst0 + (unsigned)(r*16*MB_STRIDE)*4u, b1src + (size_t)(r*16)*NI);
        cp16(b3_dst0 + (unsigned)(r*16*MB_STRIDE)*4u, b3src + (size_t)(r*16)*NI);
    }
    cp_commit();

    for (int it = 0; it < nkt; it++) {
        int cur = it & 1;
        if (it + 1 < nkt) {
            int nb = (it + 1) & 1;
            int k0 = (it + 1) << 5;
            unsigned ad  = a_dst0  + (unsigned)(nb*MOE_STAGE)*4u;
            unsigned b1d = b1_dst0 + (unsigned)(nb*MOE_STAGE)*4u;
            unsigned b3d = b3_dst0 + (unsigned)(nb*MOE_STAGE)*4u;
            #pragma unroll
            for (int r = 0; r < 4; r++)
                cp16(ad + (unsigned)(r*32*MA_STRIDE)*4u, aptr[r] + k0 + ak4);
            #pragma unroll
            for (int r = 0; r < 2; r++) {
                cp16(b1d + (unsigned)(r*16*MB_STRIDE)*4u, b1src + (size_t)(k0 + r*16)*NI);
                cp16(b3d + (unsigned)(r*16*MB_STRIDE)*4u, b3src + (size_t)(k0 + r*16)*NI);
            }
            cp_commit();
            cp_wait<1>();
        } else {
            cp_wait<0>();
        }
        __syncthreads();
        const float* Ac  = dsm + cur*MOE_STAGE;
        const float* B1c = Ac + MA_BUF;
        const float* B3c = B1c + MB_BUF;
        #pragma unroll
        for (int ks = 0; ks < 4; ks++) {
            int k8 = ks*8;
            unsigned af[2][4], b1f[4][2], b3f[4][2];
            #pragma unroll
            for (int mt=0; mt<2; mt++) {
                int m0 = warp_m*32 + mt*16;
                const float* p = &Ac[(m0+lq)*MA_STRIDE + k8 + lr];
                af[mt][0] = __float_as_uint(p[0]);
                af[mt][1] = __float_as_uint(p[8*MA_STRIDE]);
                af[mt][2] = __float_as_uint(p[4]);
                af[mt][3] = __float_as_uint(p[8*MA_STRIDE+4]);
            }
            #pragma unroll
            for (int nt=0; nt<4; nt++) {
                int n0 = warp_n*32 + nt*8 + lq;
                b1f[nt][0] = __float_as_uint(B1c[(k8+lr)*MB_STRIDE + n0]);
                b1f[nt][1] = __float_as_uint(B1c[(k8+4+lr)*MB_STRIDE + n0]);
                b3f[nt][0] = __float_as_uint(B3c[(k8+lr)*MB_STRIDE + n0]);
                b3f[nt][1] = __float_as_uint(B3c[(k8+4+lr)*MB_STRIDE + n0]);
            }
            #pragma unroll
            for (int mt=0; mt<2; mt++)
                #pragma unroll
                for (int nt=0; nt<4; nt++) {
                    MMA_TF32(acc1[mt][nt][0], acc1[mt][nt][1], acc1[mt][nt][2], acc1[mt][nt][3],
                             af[mt][0], af[mt][1], af[mt][2], af[mt][3],
                             b1f[nt][0], b1f[nt][1]);
                    MMA_TF32(acc3[mt][nt][0], acc3[mt][nt][1], acc3[mt][nt][2], acc3[mt][nt][3],
                             af[mt][0], af[mt][1], af[mt][2], af[mt][3],
                             b3f[nt][0], b3f[nt][1]);
                }
        }
        __syncthreads();
    }
    #pragma unroll
    for (int mt=0; mt<2; mt++) {
        int row0 = bm + warp_m*32 + mt*16 + lq;
        #pragma unroll
        for (int half=0; half<2; half++) {
            int row = row0 + half*8;
            if (row >= cnt) continue;
            size_t crow = (size_t)(off + row);
            #pragma unroll
            for (int nt=0; nt<4; nt++) {
                int col = bn + warp_n*32 + nt*8 + 2*lr;
                float gg0 = acc1[mt][nt][half*2+0], uu0 = acc3[mt][nt][half*2+0];
                float gg1 = acc1[mt][nt][half*2+1], uu1 = acc3[mt][nt][half*2+1];
                float2 v;
                v.x = f2tff(gg0 / (1.f + __expf(-gg0)) * uu0);
                v.y = f2tff(gg1 / (1.f + __expf(-gg1)) * uu1);
                *(float2*)(g_g + crow*NI + col) = v;
            }
        }
    }
}

// ---------------- RoPE (rounds q,k; also rounds v) ----------------
__global__ void rope_kernel() {
    int idx = blockIdx.x*256 + threadIdx.x;
    const int totq = Ttok*NH*(HDv/2);
    const int totk = totq + Ttok*KVHv*(HDv/2);
    const int tot  = totk + Ttok*(KVD/2);
    if (idx >= tot) return;
    if (idx >= totk) {
        int id2 = idx - totk;
        float* p = g_v + (size_t)id2*2;
        p[0] = f2tff(p[0]); p[1] = f2tff(p[1]);
        return;
    }
    float* base; int t, i;
    if (idx < totq) {
        i = idx & 63;
        int hh = (idx >> 6) & (NH-1);
        t = idx >> 10;
        base = g_q + (size_t)t*Dm + hh*HDv + 2*i;
    } else {
        int id2 = idx - totq;
        i = id2 & 63;
        int hh = (id2 >> 6) & (KVHv-1);
        t = id2 >> 8;
        base = g_k + (size_t)t*KVD + hh*HDv + 2*i;
    }
    int pos = t & (Lq-1);
    float inv = exp2f(-(float)i * (13.287712379549449f/64.f));
    float ang = (float)pos * inv;
    float c = cosf(ang), s = sinf(ang);
    float xr = base[0], xi = base[1];
    base[0] = f2tff(xr*c - xi*s);
    base[1] = f2tff(xr*s + xi*c);
}

// ---------------- flash attention: 64-row Q blocks, 3-stage K/V, 2 CTAs/SM ----------------
#define QPAD 132
#define VPAD 136
#define PPAD 36
#define AT_KS 0
#define AT_KBUF (32*QPAD)                     /* 4224  */
#define AT_VS (3*AT_KBUF)                     /* 12672 */
#define AT_VBUF (32*VPAD)                     /* 4352  */
#define AT_PS (AT_VS + 3*AT_VBUF)             /* 25728 */
#define AT_QS AT_KBUF                         /* Q staged in K buf1+buf2 (8448 words) */
#define AT_SMEM_WORDS (AT_PS + 64*PPAD)       /* 28032 -> 112128 B, 2 CTAs/SM */

__global__ void __launch_bounds__(128, 2) attn_mma_kernel() {
    extern __shared__ float sm[];
    int b = blockIdx.z, h = blockIdx.y;
    int q0 = blockIdx.x * 64;
    int kvh = h >> 2;
    int tid = threadIdx.x;
    int lane = tid & 31, w = tid >> 5;
    int lq = lane >> 2, lr = lane & 3;
    const float scale = 0.08838834764831845f;

    unsigned sm_base = (unsigned)__cvta_generic_to_shared(sm);
    int ntiles = (q0 + 64) / 32;

    // prologue: tile 0 -> buf 0 (commit group #1)
    for (int idx = tid; idx < 32*32; idx += 128) {
        int row = idx >> 5, c4 = (idx & 31) * 4;
        size_t goff = (size_t)(b*Lq + row)*KVD + kvh*HDv + c4;
        cp16(sm_base + (unsigned)(AT_KS + row*QPAD + c4)*4u, g_k + goff);
        cp16(sm_base + (unsigned)(AT_VS + row*VPAD + c4)*4u, g_v + goff);
    }
    cp_commit();

    // stage Q into the (currently free) K buf1+buf2 region, lift to registers
    for (int idx = tid; idx < 64*32; idx += 128) {
        int row = idx >> 5, c4 = (idx & 31) * 4;
        float4 qv = *(const float4*)(g_q + (size_t)(b*Lq + q0 + row)*Dm + h*HDv + c4);
        *(float4*)&sm[AT_QS + row*QPAD + c4] = qv;
    }
    __syncthreads();
    unsigned qf[16][4];
    #pragma unroll
    for (int ks = 0; ks < 16; ks++) {
        int k8 = ks*8;
        const float* qp = &sm[AT_QS + (w*16+lq)*QPAD + k8 + lr];
        qf[ks][0] = __float_as_uint(qp[0]);
        qf[ks][1] = __float_as_uint(qp[8*QPAD]);
        qf[ks][2] = __float_as_uint(qp[4]);
        qf[ks][3] = __float_as_uint(qp[8*QPAD+4]);
    }
    __syncthreads();   // all Q reads done before prefetch may overwrite buf1/buf2

    // prologue: tile 1 -> buf 1 (commit group #2)
    if (ntiles > 1) {
        for (int idx = tid; idx < 32*32; idx += 128) {
            int row = idx >> 5, c4 = (idx & 31) * 4;
            size_t goff = (size_t)(b*Lq + 32 + row)*KVD + kvh*HDv + c4;
            cp16(sm_base + (unsigned)(AT_KS + AT_KBUF + row*QPAD + c4)*4u, g_k + goff);
            cp16(sm_base + (unsigned)(AT_VS + AT_VBUF + row*VPAD + c4)*4u, g_v + goff);
        }
        cp_commit();
    }

    float o[16][4];
    #pragma unroll
    for (int nt=0;nt<16;nt++){o[nt][0]=0.f;o[nt][1]=0.f;o[nt][2]=0.f;o[nt][3]=0.f;}
    float m0 = -1e30f, m1 = -1e30f, l0 = 0.f, l1 = 0.f;
    int row_base = q0 + w*16;

    for (int kt = 0; kt < ntiles; kt++) {
        if (kt + 1 < ntiles) cp_wait<1>(); else cp_wait<0>();
        __syncthreads();
        // prefetch tile kt+2 into buf (kt+2)%3 (last computed at kt-1, safe after sync)
        if (kt + 2 < ntiles) {
            int nb = (kt + 2) % 3;
            int nbase = (kt + 2) * 32;
            for (int idx = tid; idx < 32*32; idx += 128) {
                int row = idx >> 5, c4 = (idx & 31) * 4;
                size_t goff = (size_t)(b*Lq + nbase + row)*KVD + kvh*HDv + c4;
                cp16(sm_base + (unsigned)(AT_KS + nb*AT_KBUF + row*QPAD + c4)*4u, g_k + goff);
                cp16(sm_base + (unsigned)(AT_VS + nb*AT_VBUF + row*VPAD + c4)*4u, g_v + goff);
            }
            cp_commit();
        }
        int cur = kt % 3;
        int base = kt * 32;
        const float* Kc = sm + AT_KS + cur*AT_KBUF;
        const float* Vc = sm + AT_VS + cur*AT_VBUF;

        // skip tiles entirely above this warp's diagonal (bit-identical state)
        if (base <= row_base + 15) {
            float s[4][4];
            #pragma unroll
            for (int nt=0;nt<4;nt++){s[nt][0]=0.f;s[nt][1]=0.f;s[nt][2]=0.f;s[nt][3]=0.f;}
            #pragma unroll
            for (int ks = 0; ks < 16; ks++) {
                int k8 = ks*8;
                #pragma unroll
                for (int nt=0; nt<4; nt++) {
                    unsigned b0 = __float_as_uint(Kc[(nt*8+lq)*QPAD + k8 + lr]);
                    unsigned b1 = __float_as_uint(Kc[(nt*8+lq)*QPAD + k8 + lr + 4]);
                    MMA_TF32(s[nt][0], s[nt][1], s[nt][2], s[nt][3],
                             qf[ks][0], qf[ks][1], qf[ks][2], qf[ks][3], b0, b1);
                }
            }
            #pragma unroll
            for (int nt=0; nt<4; nt++) {
                s[nt][0]*=scale; s[nt][1]*=scale; s[nt][2]*=scale; s[nt][3]*=scale;
            }

            if (base + 31 > row_base) {
                int i0 = row_base + lq, i1 = row_base + lq + 8;
                #pragma unroll
                for (int nt=0; nt<4; nt++) {
                    int j = base + nt*8 + 2*lr;
                    if (j   > i0) s[nt][0] = -1e30f;
                    if (j+1 > i0) s[nt][1] = -1e30f;
                    if (j   > i1) s[nt][2] = -1e30f;
                    if (j+1 > i1) s[nt][3] = -1e30f;
                }
            }

            float mx0 = -1e30f, mx1 = -1e30f;
            #pragma unroll
            for (int nt=0; nt<4; nt++) {
                mx0 = fmaxf(mx0, fmaxf(s[nt][0], s[nt][1]));
                mx1 = fmaxf(mx1, fmaxf(s[nt][2], s[nt][3]));
            }
            mx0 = fmaxf(mx0, __shfl_xor_sync(0xffffffffu, mx0, 1));
            mx0 = fmaxf(mx0, __shfl_xor_sync(0xffffffffu, mx0, 2));
            mx1 = fmaxf(mx1, __shfl_xor_sync(0xffffffffu, mx1, 1));
            mx1 = fmaxf(mx1, __shfl_xor_sync(0xffffffffu, mx1, 2));
            float mn0 = fmaxf(m0, mx0), mn1 = fmaxf(m1, mx1);
            float al0 = __expf(m0 - mn0), al1 = __expf(m1 - mn1);
            float rs0 = 0.f, rs1 = 0.f;
            #pragma unroll
            for (int nt=0; nt<4; nt++) {
                s[nt][0] = __expf(s[nt][0] - mn0);
                s[nt][1] = __expf(s[nt][1] - mn0);
                s[nt][2] = __expf(s[nt][2] - mn1);
                s[nt][3] = __expf(s[nt][3] - mn1);
                rs0 += s[nt][0] + s[nt][1];
                rs1 += s[nt][2] + s[nt][3];
            }
            rs0 += __shfl_xor_sync(0xffffffffu, rs0, 1);
            rs0 += __shfl_xor_sync(0xffffffffu, rs0, 2);
            rs1 += __shfl_xor_sync(0xffffffffu, rs1, 1);
            rs1 += __shfl_xor_sync(0xffffffffu, rs1, 2);
            l0 = l0*al0 + rs0;
            l1 = l1*al1 + rs1;
            m0 = mn0; m1 = mn1;
            #pragma unroll
            for (int nt=0; nt<16; nt++) {
                o[nt][0]*=al0; o[nt][1]*=al0; o[nt][2]*=al1; o[nt][3]*=al1;
            }

            // stage P (tf32) into per-warp smem rows (dedicated region)
            #pragma unroll
            for (int nt=0; nt<4; nt++) {
                float* p0 = &sm[AT_PS + (w*16+lq)*PPAD + nt*8 + 2*lr];
                p0[0] = __uint_as_float(f2tf(s[nt][0]));
                p0[1] = __uint_as_float(f2tf(s[nt][1]));
                float* p1 = &sm[AT_PS + (w*16+lq+8)*PPAD + nt*8 + 2*lr];
                p1[0] = __uint_as_float(f2tf(s[nt][2]));
                p1[1] = __uint_as_float(f2tf(s[nt][3]));
            }
            __syncwarp();

            #pragma unroll
            for (int ks = 0; ks < 4; ks++) {
                int k8 = ks*8;
                const float* pp = &sm[AT_PS + (w*16+lq)*PPAD + k8 + lr];
                unsigned a0 = __float_as_uint(pp[0]);
                unsigned a1 = __float_as_uint(pp[8*PPAD]);
                unsigned a2 = __float_as_uint(pp[4]);
                unsigned a3 = __float_as_uint(pp[8*PPAD+4]);
                #pragma unroll
                for (int nt=0; nt<16; nt++) {
                    unsigned b0 = __float_as_uint(Vc[(k8+lr)*VPAD + nt*8 + lq]);
                    unsigned b1 = __float_as_uint(Vc[(k8+lr+4)*VPAD + nt*8 + lq]);
                    MMA_TF32(o[nt][0], o[nt][1], o[nt][2], o[nt][3],
                             a0, a1, a2, a3, b0, b1);
                }
            }
        }
    }

    float inv0 = 1.f / l0, inv1 = 1.f / l1;
    int t0 = b*Lq + row_base + lq;
    #pragma unroll
    for (int nt=0; nt<16; nt++) {
        int col = h*HDv + nt*8 + 2*lr;
        float2 v0 = make_float2(f2tff(o[nt][0]*inv0), f2tff(o[nt][1]*inv0));
        float2 v1 = make_float2(f2tff(o[nt][2]*inv1), f2tff(o[nt][3]*inv1));
        *(float2*)(g_ao + (size_t)t0*Dm + col) = v0;
        *(float2*)(g_ao + (size_t)(t0+8)*Dm + col) = v1;
    }
}

// ---------------- gating ----------------
__global__ void gate_kernel(const float* __restrict__ gw) {
    int t = blockIdx.x;
    int warp = threadIdx.x >> 5, lane = threadIdx.x & 31;
    const float* row = g_h + (size_t)t*Dm;
    float s = 0.f;
    for (int i = lane; i < Dm; i += 32) s += row[i] * gw[(size_t)i*NE + warp];
    for (int o = 16; o; o >>= 1) s += __shfl_xor_sync(0xffffffffu, s, o);
    __shared__ float logits[NE];
    if (lane == 0) logits[warp] = s;
    __syncthreads();
    if (threadIdx.x == 0) {
        float mx = logits[0];
        for (int e = 1; e < NE; e++) mx = fmaxf(mx, logits[e]);
        float ex[NE]; float sum = 0.f;
        for (int e = 0; e < NE; e++) { ex[e] = expf(logits[e]-mx); sum += ex[e]; }
        float invs = 1.f/sum;
        float sc[NE];
        for (int e = 0; e < NE; e++) { sc[e] = ex[e]*invs; g_scores[t*NE+e] = sc[e]; }
        int e0 = 0; float m0 = sc[0];
        for (int e = 1; e < NE; e++) if (sc[e] > m0) { m0 = sc[e]; e0 = e; }
        int e1 = -1; float m1 = -1.f;
        for (int e = 0; e < NE; e++) if (e != e0 && sc[e] > m1) { m1 = sc[e]; e1 = e; }
        float wsum = m0 + m1;
        g_top_idx[t*2]   = e0;  g_top_idx[t*2+1] = e1;
        g_top_w[t*2]     = m0/wsum;
        g_top_w[t*2+1]   = m1/wsum;
        atomicAdd(&g_counts[e0], 1);
        atomicAdd(&g_counts[e1], 1);
    }
}

__global__ void finalize_gate_kernel(float* aux_out) {
    int warp = threadIdx.x >> 5, lane = threadIdx.x & 31;
    float s = 0.f;
    for (int t = lane; t < Ttok; t += 32) s += g_scores[t*NE + warp];
    for (int o = 16; o; o >>= 1) s += __shfl_xor_sync(0xffffffffu, s, o);
    __shared__ float ps[NE];
    if (lane == 0) ps[warp] = s;
    __syncthreads();
    if (threadIdx.x == 0) {
        int off = 0; float aux = 0.f;
        for (int e = 0; e < NE; e++) {
            g_offsets[e] = off; off += g_counts[e];
            float f = (float)g_counts[e] / (float)Ttok;
            float p = ps[e] / (float)Ttok;
            aux += f * p;
        }
        g_offsets[NE] = off;
        aux_out[0] = 0.01f * (float)NE * aux;
    }
}

__global__ void scatter_kernel() {
    int t = blockIdx.x*256 + threadIdx.x;
    if (t >= Ttok) return;
    for (int j = 0; j < 2; j++) {
        int e = g_top_idx[t*2+j];
        int pos = atomicAdd(&g_cursor[e], 1);
        int slot = g_offsets[e] + pos;
        g_slot_token[slot] = t;
        g_slot_w[slot] = g_top_w[t*2+j];
        g_slot_of[t*2+j] = slot;
    }
}

__global__ void final_add_kernel(float* __restrict__ out) {
    int t = blockIdx.x;
    int s0 = g_slot_of[t*2], s1 = g_slot_of[t*2+1];
    float w0 = g_slot_w[s0], w1 = g_slot_w[s1];
    for (int i = threadIdx.x*4; i < Dm; i += 256*4) {
        float4 a  = *(float4*)(out + (size_t)t*Dm + i);
        float4 y0 = *(const float4*)(g_y + (size_t)s0*Dm + i);
        float4 y1 = *(const float4*)(g_y + (size_t)s1*Dm + i);
        a.x += w0*y0.x + w1*y1.x;
        a.y += w0*y0.y + w1*y1.y;
        a.z += w0*y0.z + w1*y1.z;
        a.w += w0*y0.w + w1*y1.w;
        *(float4*)(out + (size_t)t*Dm + i) = a;
    }
}

// ---------------- launch ----------------
extern "C" void kernel_launch(void* const* d_in, const int* in_sizes, int n_in,
                              void* d_out, int out_size) {
    const float* x           = (const float*)d_in[0];
    const float* w_q         = (const float*)d_in[1];
    const float* w_k         = (const float*)d_in[2];
    const float* w_v         = (const float*)d_in[3];
    const float* w_o         = (const float*)d_in[4];
    const float* attn_norm_w = (const float*)d_in[5];
    const float* moe_norm_w  = (const float*)d_in[6];
    const float* gate_w      = (const float*)d_in[7];
    const float* w1          = (const float*)d_in[8];
    const float* w3          = (const float*)d_in[9];
    const float* w2          = (const float*)d_in[10];
    float* out = (float*)d_out;

    float *ph, *pq, *pk, *pv, *pao, *pg, *py;
    float *pwq, *pwk, *pwv, *pwo;
    cudaGetSymbolAddress((void**)&ph,  g_h);
    cudaGetSymbolAddress((void**)&pq,  g_q);
    cudaGetSymbolAddress((void**)&pk,  g_k);
    cudaGetSymbolAddress((void**)&pv,  g_v);
    cudaGetSymbolAddress((void**)&pao, g_ao);
    cudaGetSymbolAddress((void**)&pg,  g_g);
    cudaGetSymbolAddress((void**)&py,  g_y);
    cudaGetSymbolAddress((void**)&pwq, r_wq);
    cudaGetSymbolAddress((void**)&pwk, r_wk);
    cudaGetSymbolAddress((void**)&pwv, r_wv);
    cudaGetSymbolAddress((void**)&pwo, r_wo);

    static int attr_set = 0;
    const int attn_smem = AT_SMEM_WORDS * 4;
    if (!attr_set) {
        cudaFuncSetAttribute(attn_mma_kernel,
                             cudaFuncAttributeMaxDynamicSharedMemorySize, attn_smem);
        cudaFuncSetAttribute(tf32_gemm,
                             cudaFuncAttributeMaxDynamicSharedMemorySize, GEMM_SMEM);
        cudaFuncSetAttribute(moe13_gemm,
                             cudaFuncAttributeMaxDynamicSharedMemorySize, MOE_SMEM);
        attr_set = 1;
    }

    roundcopy<<<(Dm*Dm/4 + 255)/256, 256>>>(w_q, pwq, Dm*Dm/4);
    roundcopy<<<(Dm*KVD/4 + 255)/256, 256>>>(w_k, pwk, Dm*KVD/4);
    roundcopy<<<(Dm*KVD/4 + 255)/256, 256>>>(w_v, pwv, Dm*KVD/4);
    roundcopy<<<(Dm*Dm/4 + 255)/256, 256>>>(w_o, pwo, Dm*Dm/4);

    zero_kernel<<<1, 32>>>();
    rmsnorm_kernel<<<Ttok, 256>>>(x, attn_norm_w, ph);
    tf32_gemm<<<dim3(Dm/128, Ttok/128, 1), 256, GEMM_SMEM>>>(ph, pwq, pq, Ttok, Dm, Dm,
                                                  nullptr, 0, nullptr, nullptr);
    tf32_gemm<<<dim3(KVD/128, Ttok/128, 2), 256, GEMM_SMEM>>>(ph, pwk, pk, Ttok, KVD, Dm,
                                                   nullptr, 0, pwv, pv);
    {
        int tot = Ttok*NH*(HDv/2) + Ttok*KVHv*(HDv/2) + Ttok*(KVD/2);
        rope_kernel<<<(tot + 255)/256, 256>>>();
    }
    attn_mma_kernel<<<dim3(Lq/64, NH, Bq), 128, attn_smem>>>();
    tf32_gemm<<<dim3(Dm/128, Ttok/128, 1), 256, GEMM_SMEM>>>(pao, pwo, out, Ttok, Dm, Dm,
                                                  x, 0, nullptr, nullptr);
    rmsnorm_kernel<<<Ttok, 256>>>(out, moe_norm_w, ph);
    gate_kernel<<<Ttok, 256>>>(gate_w);
    finalize_gate_kernel<<<1, 256>>>(out + (size_t)Ttok*Dm);
    scatter_kernel<<<(Ttok + 255)/256, 256>>>();
    moe13_gemm<<<dim3(NI/64, SLOTS/128, NE), 256, MOE_SMEM>>>(w1, w3);
    tf32_gemm<<<dim3(Dm/128, SLOTS/128, NE), 256, GEMM_SMEM>>>(pg, w2, py, 0, Dm, NI,
                                                    nullptr, 2, nullptr, nullptr);
    final_add_kernel<<<Ttok, 256>>>(out);
}

// round 15
// speedup vs baseline: 1.0259x; 1.0053x over previous
#include <cuda_runtime.h>
#include <math.h>

#define Bq 2
#define Lq 2048
#define Dm 2048
#define NH 16
#define HDv 128
#define KVHv 4
#define NE 8
#define NI 1024
#define Ttok (Bq*Lq)          /* 4096 */
#define KVD (KVHv*HDv)        /* 512  */
#define SLOTS (Ttok*2)        /* 8192 */

// ---------------- scratch ----------------
__device__ float g_h[Ttok*Dm];
__device__ float g_q[Ttok*Dm];
__device__ float g_k[Ttok*KVD];
__device__ float g_v[Ttok*KVD];
__device__ float g_ao[Ttok*Dm];
__device__ float g_g[SLOTS*NI];
__device__ float g_y[SLOTS*Dm];
__device__ float g_scores[Ttok*NE];
__device__ int   g_counts[NE];
__device__ int   g_offsets[NE+1];
__device__ int   g_cursor[NE];
__device__ int   g_top_idx[Ttok*2];
__device__ float g_top_w[Ttok*2];
__device__ int   g_slot_token[SLOTS];
__device__ float g_slot_w[SLOTS];
__device__ int   g_slot_of[Ttok*2];
__device__ float r_wq[Dm*Dm];
__device__ float r_wk[Dm*KVD];
__device__ float r_wv[Dm*KVD];
__device__ float r_wo[Dm*Dm];

__device__ __forceinline__ unsigned f2tf(float x) {
    unsigned r; asm("cvt.rna.tf32.f32 %0, %1;" : "=r"(r) : "f"(x)); return r;
}
__device__ __forceinline__ float f2tff(float x) { return __uint_as_float(f2tf(x)); }
__device__ __forceinline__ void cp16(unsigned d, const void* s) {
    asm volatile("cp.async.cg.shared.global [%0], [%1], 16;" :: "r"(d), "l"(s));
}
__device__ __forceinline__ void cp_commit() {
    asm volatile("cp.async.commit_group;");
}
template<int N> __device__ __forceinline__ void cp_wait() {
    asm volatile("cp.async.wait_group %0;" :: "n"(N));
}
#define MMA_TF32(d0,d1,d2,d3,a0,a1,a2,a3,b0,b1) \
    asm volatile( \
        "mma.sync.aligned.m16n8k8.row.col.f32.tf32.tf32.f32 " \
        "{%0,%1,%2,%3}, {%4,%5,%6,%7}, {%8,%9}, {%0,%1,%2,%3};" \
        : "+f"(d0), "+f"(d1), "+f"(d2), "+f"(d3) \
        : "r"(a0), "r"(a1), "r"(a2), "r"(a3), "r"(b0), "r"(b1))

// ---------------- small kernels ----------------
__global__ void zero_kernel() {
    int i = threadIdx.x;
    if (i < NE) { g_counts[i] = 0; g_cursor[i] = 0; }
}

__global__ void roundcopy(const float* __restrict__ s, float* __restrict__ d, int n4) {
    int i = blockIdx.x*256 + threadIdx.x;
    if (i >= n4) return;
    float4 v = ((const float4*)s)[i];
    uint4 u;
    u.x = f2tf(v.x); u.y = f2tf(v.y); u.z = f2tf(v.z); u.w = f2tf(v.w);
    ((uint4*)d)[i] = u;
}

__global__ void rmsnorm_kernel(const float* __restrict__ in,
                               const float* __restrict__ w,
                               float* __restrict__ out) {
    int t = blockIdx.x;
    const float* row = in + (size_t)t*Dm;
    float ss = 0.f;
    for (int i = threadIdx.x; i < Dm; i += 256) { float v = row[i]; ss += v*v; }
    __shared__ float red[8];
    for (int o = 16; o; o >>= 1) ss += __shfl_xor_sync(0xffffffffu, ss, o);
    if ((threadIdx.x & 31) == 0) red[threadIdx.x >> 5] = ss;
    __syncthreads();
    float tot = 0.f;
    #pragma unroll
    for (int i = 0; i < 8; i++) tot += red[i];
    float inv = rsqrtf(tot * (1.f/(float)Dm) + 1e-5f);
    for (int i = threadIdx.x; i < Dm; i += 256)
        out[(size_t)t*Dm + i] = f2tff(row[i] * inv * w[i]);
}

// ---------------- tf32 GEMM, cp.async 2-stage, single barrier per k-tile ----------------
#define GA_STRIDE 36
#define GB_STRIDE 136
#define GA_BUF (128*GA_STRIDE)
#define GB_BUF (32*GB_STRIDE)
#define GEMM_SMEM ((2*GA_BUF + 2*GB_BUF)*4)

__global__ void __launch_bounds__(256, 2) tf32_gemm(
    const float* __restrict__ A, const float* __restrict__ B,
    float* __restrict__ C, int M, int N, int K,
    const float* __restrict__ addsrc, int mode,
    const float* __restrict__ B2, float* __restrict__ C2)
{
    extern __shared__ float dsm[];
    float* As = dsm;
    float* Bs = dsm + 2*GA_BUF;
    int cnt, off;
    if (mode == 0) {
        cnt = M; off = 0;
        if (blockIdx.z == 1) { B = B2; C = C2; }
    } else {
        int e = blockIdx.z;
        cnt = g_counts[e]; off = g_offsets[e];
        B += (size_t)e * K * N;
    }
    int bm = blockIdx.y * 128;
    if (bm >= cnt) return;
    int bn = blockIdx.x * 128;
    int tid = threadIdx.x;
    int lane = tid & 31, wid = tid >> 5;
    int warp_m = wid >> 2, warp_n = wid & 3;
    int lq = lane >> 2, lr = lane & 3;

    const float* aptr[4];
    #pragma unroll
    for (int r = 0; r < 4; r++) {
        int row = bm + r*32 + (tid >> 3);
        int re = row < cnt ? row : cnt - 1;
        if (mode == 1)      aptr[r] = g_h + (size_t)g_slot_token[off + re] * K;
        else if (mode == 2) aptr[r] = A + (size_t)(off + re) * K;
        else                aptr[r] = A + (size_t)re * K;
    }
    int ak4 = (tid & 7) * 4;
    int bk  = tid >> 5;
    int bn4 = lane * 4;
    const float* bsrc = B + (size_t)bk*N + bn + bn4;

    unsigned as_sm = (unsigned)__cvta_generic_to_shared(As);
    unsigned bs_sm = (unsigned)__cvta_generic_to_shared(Bs);
    unsigned a_dst0 = as_sm + (((tid>>3)*GA_STRIDE) + ak4)*4u;
    unsigned b_dst0 = bs_sm + ((bk*GB_STRIDE) + bn4)*4u;

    float acc[4][4][4];
    #pragma unroll
    for (int i=0;i<4;i++)
        #pragma unroll
        for(int j=0;j<4;j++)
            #pragma unroll
            for(int c=0;c<4;c++) acc[i][j][c]=0.f;

    int nkt = K >> 5;
    // prologue: tile 0 -> buf 0
    #pragma unroll
    for (int r = 0; r < 4; r++)
        cp16(a_dst0 + (unsigned)(r*32*GA_STRIDE)*4u, aptr[r] + ak4);
    #pragma unroll
    for (int r = 0; r < 4; r++)
        cp16(b_dst0 + (unsigned)(r*8*GB_STRIDE)*4u, bsrc + (size_t)(r*8)*N);
    cp_commit();

    for (int it = 0; it < nkt; it++) {
        int cur = it & 1;
        cp_wait<0>();           // tile it arrived (only outstanding group)
        __syncthreads();        // visible to all warps; compute(it-1) fully done
        if (it + 1 < nkt) {     // prefetch tile it+1 into the vacated buffer
            int nb = (it + 1) & 1;
            int k0 = (it + 1) << 5;
            unsigned ad = a_dst0 + (unsigned)(nb*GA_BUF)*4u;
            unsigned bd = b_dst0 + (unsigned)(nb*GB_BUF)*4u;
            #pragma unroll
            for (int r = 0; r < 4; r++)
                cp16(ad + (unsigned)(r*32*GA_STRIDE)*4u, aptr[r] + k0 + ak4);
            #pragma unroll
            for (int r = 0; r < 4; r++)
                cp16(bd + (unsigned)(r*8*GB_STRIDE)*4u, bsrc + (size_t)(k0 + r*8)*N);
            cp_commit();
        }
        const float* Ac = As + cur*GA_BUF;
        const float* Bc = Bs + cur*GB_BUF;
        #pragma unroll
        for (int ks = 0; ks < 4; ks++) {
            int k8 = ks*8;
            unsigned af[4][4], bf[4][2];
            #pragma unroll
            for (int mt=0; mt<4; mt++) {
                int m0 = warp_m*64 + mt*16;
                const float* p = &Ac[(m0+lq)*GA_STRIDE + k8 + lr];
                af[mt][0] = __float_as_uint(p[0]);
                af[mt][1] = __float_as_uint(p[8*GA_STRIDE]);
                af[mt][2] = __float_as_uint(p[4]);
                af[mt][3] = __float_as_uint(p[8*GA_STRIDE+4]);
            }
            #pragma unroll
            for (int nt=0; nt<4; nt++) {
                int n0 = warp_n*32 + nt*8 + lq;
                bf[nt][0] = __float_as_uint(Bc[(k8+lr)*GB_STRIDE + n0]);
                bf[nt][1] = __float_as_uint(Bc[(k8+4+lr)*GB_STRIDE + n0]);
            }
            #pragma unroll
            for (int mt=0; mt<4; mt++)
                #pragma unroll
                for (int nt=0; nt<4; nt++)
                    MMA_TF32(acc[mt][nt][0], acc[mt][nt][1], acc[mt][nt][2], acc[mt][nt][3],
                             af[mt][0], af[mt][1], af[mt][2], af[mt][3],
                             bf[nt][0], bf[nt][1]);
        }
    }
    #pragma unroll
    for (int mt=0; mt<4; mt++) {
        int row0 = bm + warp_m*64 + mt*16 + lq;
        #pragma unroll
        for (int half=0; half<2; half++) {
            int row = row0 + half*8;
            if (row >= cnt) continue;
            size_t crow = (size_t)(off + row);
            #pragma unroll
            for (int nt=0; nt<4; nt++) {
                int col = bn + warp_n*32 + nt*8 + 2*lr;
                float2 v;
                v.x = acc[mt][nt][half*2+0];
                v.y = acc[mt][nt][half*2+1];
                if (addsrc) {
                    float2 s = *(const float2*)(addsrc + crow*N + col);
                    v.x += s.x; v.y += s.y;
                }
                *(float2*)(C + crow*N + col) = v;
            }
        }
    }
}

// ---------------- fused MoE up-proj, single barrier per k-tile ----------------
#define MA_STRIDE 36
#define MB_STRIDE 72
#define MA_BUF (128*MA_STRIDE)
#define MB_BUF (32*MB_STRIDE)
#define MOE_STAGE (MA_BUF + 2*MB_BUF)
#define MOE_SMEM (2*MOE_STAGE*4)

__global__ void __launch_bounds__(256, 2) moe13_gemm(
    const float* __restrict__ W1, const float* __restrict__ W3)
{
    extern __shared__ float dsm[];
    int e = blockIdx.z;
    int cnt = g_counts[e], off = g_offsets[e];
    int bm = blockIdx.y * 128;
    if (bm >= cnt) return;
    int bn = blockIdx.x * 64;
    int tid = threadIdx.x;
    int lane = tid & 31, wid = tid >> 5;
    int warp_m = wid >> 1, warp_n = wid & 1;
    int lq = lane >> 2, lr = lane & 3;

    const float* W1e = W1 + (size_t)e*Dm*NI;
    const float* W3e = W3 + (size_t)e*Dm*NI;

    const float* aptr[4];
    #pragma unroll
    for (int r = 0; r < 4; r++) {
        int row = bm + r*32 + (tid >> 3);
        int re = row < cnt ? row : cnt - 1;
        aptr[r] = g_h + (size_t)g_slot_token[off + re] * Dm;
    }
    int ak4 = (tid & 7) * 4;
    int brow = tid >> 4;
    int bc4  = (tid & 15) * 4;
    const float* b1src = W1e + (size_t)brow*NI + bn + bc4;
    const float* b3src = W3e + (size_t)brow*NI + bn + bc4;

    unsigned sm0 = (unsigned)__cvta_generic_to_shared(dsm);
    unsigned a_dst0  = sm0 + (((tid>>3)*MA_STRIDE) + ak4)*4u;
    unsigned b1_dst0 = sm0 + (unsigned)(MA_BUF + brow*MB_STRIDE + bc4)*4u;
    unsigned b3_dst0 = b1_dst0 + (unsigned)(MB_BUF)*4u;

    float acc1[2][4][4], acc3[2][4][4];
    #pragma unroll
    for (int i=0;i<2;i++)
        #pragma unroll
        for(int j=0;j<4;j++)
            #pragma unroll
            for(int c=0;c<4;c++){acc1[i][j][c]=0.f;acc3[i][j][c]=0.f;}

    const int nkt = Dm >> 5;
    #pragma unroll
    for (int r = 0; r < 4; r++)
        cp16(a_dst0 + (unsigned)(r*32*MA_STRIDE)*4u, aptr[r] + ak4);
    #pragma unroll
    for (int r = 0; r < 2; r++) {
        cp16(b1_dst0 + (unsigned)(r*16*MB_STRIDE)*4u, b1src + (size_t)(r*16)*NI);
        cp16(b3_dst0 + (unsigned)(r*16*MB_STRIDE)*4u, b3src + (size_t)(r*16)*NI);
    }
    cp_commit();

    for (int it = 0; it < nkt; it++) {
        int cur = it & 1;
        cp_wait<0>();
        __syncthreads();
        if (it + 1 < nkt) {
            int nb = (it + 1) & 1;
            int k0 = (it + 1) << 5;
            unsigned ad  = a_dst0  + (unsigned)(nb*MOE_STAGE)*4u;
            unsigned b1d = b1_dst0 + (unsigned)(nb*MOE_STAGE)*4u;
            unsigned b3d = b3_dst0 + (unsigned)(nb*MOE_STAGE)*4u;
            #pragma unroll
            for (int r = 0; r < 4; r++)
                cp16(ad + (unsigned)(r*32*MA_STRIDE)*4u, aptr[r] + k0 + ak4);
            #pragma unroll
            for (int r = 0; r < 2; r++) {
                cp16(b1d + (unsigned)(r*16*MB_STRIDE)*4u, b1src + (size_t)(k0 + r*16)*NI);
                cp16(b3d + (unsigned)(r*16*MB_STRIDE)*4u, b3src + (size_t)(k0 + r*16)*NI);
            }
            cp_commit();
        }
        const float* Ac  = dsm + cur*MOE_STAGE;
        const float* B1c = Ac + MA_BUF;
        const float* B3c = B1c + MB_BUF;
        #pragma unroll
        for (int ks = 0; ks < 4; ks++) {
            int k8 = ks*8;
            unsigned af[2][4], b1f[4][2], b3f[4][2];
            #pragma unroll
            for (int mt=0; mt<2; mt++) {
                int m0 = warp_m*32 + mt*16;
                const float* p = &Ac[(m0+lq)*MA_STRIDE + k8 + lr];
                af[mt][0] = __float_as_uint(p[0]);
                af[mt][1] = __float_as_uint(p[8*MA_STRIDE]);
                af[mt][2] = __float_as_uint(p[4]);
                af[mt][3] = __float_as_uint(p[8*MA_STRIDE+4]);
            }
            #pragma unroll
            for (int nt=0; nt<4; nt++) {
                int n0 = warp_n*32 + nt*8 + lq;
                b1f[nt][0] = __float_as_uint(B1c[(k8+lr)*MB_STRIDE + n0]);
                b1f[nt][1] = __float_as_uint(B1c[(k8+4+lr)*MB_STRIDE + n0]);
                b3f[nt][0] = __float_as_uint(B3c[(k8+lr)*MB_STRIDE + n0]);
                b3f[nt][1] = __float_as_uint(B3c[(k8+4+lr)*MB_STRIDE + n0]);
            }
            #pragma unroll
            for (int mt=0; mt<2; mt++)
                #pragma unroll
                for (int nt=0; nt<4; nt++) {
                    MMA_TF32(acc1[mt][nt][0], acc1[mt][nt][1], acc1[mt][nt][2], acc1[mt][nt][3],
                             af[mt][0], af[mt][1], af[mt][2], af[mt][3],
                             b1f[nt][0], b1f[nt][1]);
                    MMA_TF32(acc3[mt][nt][0], acc3[mt][nt][1], acc3[mt][nt][2], acc3[mt][nt][3],
                             af[mt][0], af[mt][1], af[mt][2], af[mt][3],
                             b3f[nt][0], b3f[nt][1]);
                }
        }
    }
    #pragma unroll
    for (int mt=0; mt<2; mt++) {
        int row0 = bm + warp_m*32 + mt*16 + lq;
        #pragma unroll
        for (int half=0; half<2; half++) {
            int row = row0 + half*8;
            if (row >= cnt) continue;
            size_t crow = (size_t)(off + row);
            #pragma unroll
            for (int nt=0; nt<4; nt++) {
                int col = bn + warp_n*32 + nt*8 + 2*lr;
                float gg0 = acc1[mt][nt][half*2+0], uu0 = acc3[mt][nt][half*2+0];
                float gg1 = acc1[mt][nt][half*2+1], uu1 = acc3[mt][nt][half*2+1];
                float2 v;
                v.x = f2tff(gg0 / (1.f + __expf(-gg0)) * uu0);
                v.y = f2tff(gg1 / (1.f + __expf(-gg1)) * uu1);
                *(float2*)(g_g + crow*NI + col) = v;
            }
        }
    }
}

// ---------------- RoPE (rounds q,k; also rounds v) ----------------
__global__ void rope_kernel() {
    int idx = blockIdx.x*256 + threadIdx.x;
    const int totq = Ttok*NH*(HDv/2);
    const int totk = totq + Ttok*KVHv*(HDv/2);
    const int tot  = totk + Ttok*(KVD/2);
    if (idx >= tot) return;
    if (idx >= totk) {
        int id2 = idx - totk;
        float* p = g_v + (size_t)id2*2;
        p[0] = f2tff(p[0]); p[1] = f2tff(p[1]);
        return;
    }
    float* base; int t, i;
    if (idx < totq) {
        i = idx & 63;
        int hh = (idx >> 6) & (NH-1);
        t = idx >> 10;
        base = g_q + (size_t)t*Dm + hh*HDv + 2*i;
    } else {
        int id2 = idx - totq;
        i = id2 & 63;
        int hh = (id2 >> 6) & (KVHv-1);
        t = id2 >> 8;
        base = g_k + (size_t)t*KVD + hh*HDv + 2*i;
    }
    int pos = t & (Lq-1);
    float inv = exp2f(-(float)i * (13.287712379549449f/64.f));
    float ang = (float)pos * inv;
    float c = cosf(ang), s = sinf(ang);
    float xr = base[0], xi = base[1];
    base[0] = f2tff(xr*c - xi*s);
    base[1] = f2tff(xr*s + xi*c);
}

// ---------------- flash attention: 64-row Q blocks, 3-stage K/V, 2 CTAs/SM ----------------
#define QPAD 132
#define VPAD 136
#define PPAD 36
#define AT_KS 0
#define AT_KBUF (32*QPAD)                     /* 4224  */
#define AT_VS (3*AT_KBUF)                     /* 12672 */
#define AT_VBUF (32*VPAD)                     /* 4352  */
#define AT_PS (AT_VS + 3*AT_VBUF)             /* 25728 */
#define AT_QS AT_KBUF                         /* Q staged in K buf1+buf2 */
#define AT_SMEM_WORDS (AT_PS + 64*PPAD)       /* 28032 -> 112128 B */

__global__ void __launch_bounds__(128, 2) attn_mma_kernel() {
    extern __shared__ float sm[];
    int b = blockIdx.z, h = blockIdx.y;
    int q0 = blockIdx.x * 64;
    int kvh = h >> 2;
    int tid = threadIdx.x;
    int lane = tid & 31, w = tid >> 5;
    int lq = lane >> 2, lr = lane & 3;
    const float scale = 0.08838834764831845f;

    unsigned sm_base = (unsigned)__cvta_generic_to_shared(sm);
    int ntiles = (q0 + 64) / 32;

    for (int idx = tid; idx < 32*32; idx += 128) {
        int row = idx >> 5, c4 = (idx & 31) * 4;
        size_t goff = (size_t)(b*Lq + row)*KVD + kvh*HDv + c4;
        cp16(sm_base + (unsigned)(AT_KS + row*QPAD + c4)*4u, g_k + goff);
        cp16(sm_base + (unsigned)(AT_VS + row*VPAD + c4)*4u, g_v + goff);
    }
    cp_commit();

    for (int idx = tid; idx < 64*32; idx += 128) {
        int row = idx >> 5, c4 = (idx & 31) * 4;
        float4 qv = *(const float4*)(g_q + (size_t)(b*Lq + q0 + row)*Dm + h*HDv + c4);
        *(float4*)&sm[AT_QS + row*QPAD + c4] = qv;
    }
    __syncthreads();
    unsigned qf[16][4];
    #pragma unroll
    for (int ks = 0; ks < 16; ks++) {
        int k8 = ks*8;
        const float* qp = &sm[AT_QS + (w*16+lq)*QPAD + k8 + lr];
        qf[ks][0] = __float_as_uint(qp[0]);
        qf[ks][1] = __float_as_uint(qp[8*QPAD]);
        qf[ks][2] = __float_as_uint(qp[4]);
        qf[ks][3] = __float_as_uint(qp[8*QPAD+4]);
    }
    __syncthreads();

    if (ntiles > 1) {
        for (int idx = tid; idx < 32*32; idx += 128) {
            int row = idx >> 5, c4 = (idx & 31) * 4;
            size_t goff = (size_t)(b*Lq + 32 + row)*KVD + kvh*HDv + c4;
            cp16(sm_base + (unsigned)(AT_KS + AT_KBUF + row*QPAD + c4)*4u, g_k + goff);
            cp16(sm_base + (unsigned)(AT_VS + AT_VBUF + row*VPAD + c4)*4u, g_v + goff);
        }
        cp_commit();
    }

    float o[16][4];
    #pragma unroll
    for (int nt=0;nt<16;nt++){o[nt][0]=0.f;o[nt][1]=0.f;o[nt][2]=0.f;o[nt][3]=0.f;}
    float m0 = -1e30f, m1 = -1e30f, l0 = 0.f, l1 = 0.f;
    int row_base = q0 + w*16;

    for (int kt = 0; kt < ntiles; kt++) {
        if (kt + 1 < ntiles) cp_wait<1>(); else cp_wait<0>();
        __syncthreads();
        if (kt + 2 < ntiles) {
            int nb = (kt + 2) % 3;
            int nbase = (kt + 2) * 32;
            for (int idx = tid; idx < 32*32; idx += 128) {
                int row = idx >> 5, c4 = (idx & 31) * 4;
                size_t goff = (size_t)(b*Lq + nbase + row)*KVD + kvh*HDv + c4;
                cp16(sm_base + (unsigned)(AT_KS + nb*AT_KBUF + row*QPAD + c4)*4u, g_k + goff);
                cp16(sm_base + (unsigned)(AT_VS + nb*AT_VBUF + row*VPAD + c4)*4u, g_v + goff);
            }
            cp_commit();
        }
        int cur = kt % 3;
        int base = kt * 32;
        const float* Kc = sm + AT_KS + cur*AT_KBUF;
        const float* Vc = sm + AT_VS + cur*AT_VBUF;

        if (base <= row_base + 15) {
            float s[4][4];
            #pragma unroll
            for (int nt=0;nt<4;nt++){s[nt][0]=0.f;s[nt][1]=0.f;s[nt][2]=0.f;s[nt][3]=0.f;}
            #pragma unroll
            for (int ks = 0; ks < 16; ks++) {
                int k8 = ks*8;
                #pragma unroll
                for (int nt=0; nt<4; nt++) {
                    unsigned b0 = __float_as_uint(Kc[(nt*8+lq)*QPAD + k8 + lr]);
                    unsigned b1 = __float_as_uint(Kc[(nt*8+lq)*QPAD + k8 + lr + 4]);
                    MMA_TF32(s[nt][0], s[nt][1], s[nt][2], s[nt][3],
                             qf[ks][0], qf[ks][1], qf[ks][2], qf[ks][3], b0, b1);
                }
            }
            #pragma unroll
            for (int nt=0; nt<4; nt++) {
                s[nt][0]*=scale; s[nt][1]*=scale; s[nt][2]*=scale; s[nt][3]*=scale;
            }

            if (base + 31 > row_base) {
                int i0 = row_base + lq, i1 = row_base + lq + 8;
                #pragma unroll
                for (int nt=0; nt<4; nt++) {
                    int j = base + nt*8 + 2*lr;
                    if (j   > i0) s[nt][0] = -1e30f;
                    if (j+1 > i0) s[nt][1] = -1e30f;
                    if (j   > i1) s[nt][2] = -1e30f;
                    if (j+1 > i1) s[nt][3] = -1e30f;
                }
            }

            float mx0 = -1e30f, mx1 = -1e30f;
            #pragma unroll
            for (int nt=0; nt<4; nt++) {
                mx0 = fmaxf(mx0, fmaxf(s[nt][0], s[nt][1]));
                mx1 = fmaxf(mx1, fmaxf(s[nt][2], s[nt][3]));
            }
            mx0 = fmaxf(mx0, __shfl_xor_sync(0xffffffffu, mx0, 1));
            mx0 = fmaxf(mx0, __shfl_xor_sync(0xffffffffu, mx0, 2));
            mx1 = fmaxf(mx1, __shfl_xor_sync(0xffffffffu, mx1, 1));
            mx1 = fmaxf(mx1, __shfl_xor_sync(0xffffffffu, mx1, 2));
            float mn0 = fmaxf(m0, mx0), mn1 = fmaxf(m1, mx1);
            float al0 = __expf(m0 - mn0), al1 = __expf(m1 - mn1);
            float rs0 = 0.f, rs1 = 0.f;
            #pragma unroll
            for (int nt=0; nt<4; nt++) {
                s[nt][0] = __expf(s[nt][0] - mn0);
                s[nt][1] = __expf(s[nt][1] - mn0);
                s[nt][2] = __expf(s[nt][2] - mn1);
                s[nt][3] = __expf(s[nt][3] - mn1);
                rs0 += s[nt][0] + s[nt][1];
                rs1 += s[nt][2] + s[nt][3];
            }
            rs0 += __shfl_xor_sync(0xffffffffu, rs0, 1);
            rs0 += __shfl_xor_sync(0xffffffffu, rs0, 2);
            rs1 += __shfl_xor_sync(0xffffffffu, rs1, 1);
            rs1 += __shfl_xor_sync(0xffffffffu, rs1, 2);
            l0 = l0*al0 + rs0;
            l1 = l1*al1 + rs1;
            m0 = mn0; m1 = mn1;
            #pragma unroll
            for (int nt=0; nt<16; nt++) {
                o[nt][0]*=al0; o[nt][1]*=al0; o[nt][2]*=al1; o[nt][3]*=al1;
            }

            #pragma unroll
            for (int nt=0; nt<4; nt++) {
                float* p0 = &sm[AT_PS + (w*16+lq)*PPAD + nt*8 + 2*lr];
                p0[0] = __uint_as_float(f2tf(s[nt][0]));
                p0[1] = __uint_as_float(f2tf(s[nt][1]));
                float* p1 = &sm[AT_PS + (w*16+lq+8)*PPAD + nt*8 + 2*lr];
                p1[0] = __uint_as_float(f2tf(s[nt][2]));
                p1[1] = __uint_as_float(f2tf(s[nt][3]));
            }
            __syncwarp();

            #pragma unroll
            for (int ks = 0; ks < 4; ks++) {
                int k8 = ks*8;
                const float* pp = &sm[AT_PS + (w*16+lq)*PPAD + k8 + lr];
                unsigned a0 = __float_as_uint(pp[0]);
                unsigned a1 = __float_as_uint(pp[8*PPAD]);
                unsigned a2 = __float_as_uint(pp[4]);
                unsigned a3 = __float_as_uint(pp[8*PPAD+4]);
                #pragma unroll
                for (int nt=0; nt<16; nt++) {
                    unsigned b0 = __float_as_uint(Vc[(k8+lr)*VPAD + nt*8 + lq]);
                    unsigned b1 = __float_as_uint(Vc[(k8+lr+4)*VPAD + nt*8 + lq]);
                    MMA_TF32(o[nt][0], o[nt][1], o[nt][2], o[nt][3],
                             a0, a1, a2, a3, b0, b1);
                }
            }
        }
    }

    float inv0 = 1.f / l0, inv1 = 1.f / l1;
    int t0 = b*Lq + row_base + lq;
    #pragma unroll
    for (int nt=0; nt<16; nt++) {
        int col = h*HDv + nt*8 + 2*lr;
        float2 v0 = make_float2(f2tff(o[nt][0]*inv0), f2tff(o[nt][1]*inv0));
        float2 v1 = make_float2(f2tff(o[nt][2]*inv1), f2tff(o[nt][3]*inv1));
        *(float2*)(g_ao + (size_t)t0*Dm + col) = v0;
        *(float2*)(g_ao + (size_t)(t0+8)*Dm + col) = v1;
    }
}

// ---------------- gating ----------------
__global__ void gate_kernel(const float* __restrict__ gw) {
    int t = blockIdx.x;
    int warp = threadIdx.x >> 5, lane = threadIdx.x & 31;
    const float* row = g_h + (size_t)t*Dm;
    float s = 0.f;
    for (int i = lane; i < Dm; i += 32) s += row[i] * gw[(size_t)i*NE + warp];
    for (int o = 16; o; o >>= 1) s += __shfl_xor_sync(0xffffffffu, s, o);
    __shared__ float logits[NE];
    if (lane == 0) logits[warp] = s;
    __syncthreads();
    if (threadIdx.x == 0) {
        float mx = logits[0];
        for (int e = 1; e < NE; e++) mx = fmaxf(mx, logits[e]);
        float ex[NE]; float sum = 0.f;
        for (int e = 0; e < NE; e++) { ex[e] = expf(logits[e]-mx); sum += ex[e]; }
        float invs = 1.f/sum;
        float sc[NE];
        for (int e = 0; e < NE; e++) { sc[e] = ex[e]*invs; g_scores[t*NE+e] = sc[e]; }
        int e0 = 0; float m0 = sc[0];
        for (int e = 1; e < NE; e++) if (sc[e] > m0) { m0 = sc[e]; e0 = e; }
        int e1 = -1; float m1 = -1.f;
        for (int e = 0; e < NE; e++) if (e != e0 && sc[e] > m1) { m1 = sc[e]; e1 = e; }
        float wsum = m0 + m1;
        g_top_idx[t*2]   = e0;  g_top_idx[t*2+1] = e1;
        g_top_w[t*2]     = m0/wsum;
        g_top_w[t*2+1]   = m1/wsum;
        atomicAdd(&g_counts[e0], 1);
        atomicAdd(&g_counts[e1], 1);
    }
}

__global__ void finalize_gate_kernel(float* aux_out) {
    int warp = threadIdx.x >> 5, lane = threadIdx.x & 31;
    float s = 0.f;
    for (int t = lane; t < Ttok; t += 32) s += g_scores[t*NE + warp];
    for (int o = 16; o; o >>= 1) s += __shfl_xor_sync(0xffffffffu, s, o);
    __shared__ float ps[NE];
    if (lane == 0) ps[warp] = s;
    __syncthreads();
    if (threadIdx.x == 0) {
        int off = 0; float aux = 0.f;
        for (int e = 0; e < NE; e++) {
            g_offsets[e] = off; off += g_counts[e];
            float f = (float)g_counts[e] / (float)Ttok;
            float p = ps[e] / (float)Ttok;
            aux += f * p;
        }
        g_offsets[NE] = off;
        aux_out[0] = 0.01f * (float)NE * aux;
    }
}

__global__ void scatter_kernel() {
    int t = blockIdx.x*256 + threadIdx.x;
    if (t >= Ttok) return;
    for (int j = 0; j < 2; j++) {
        int e = g_top_idx[t*2+j];
        int pos = atomicAdd(&g_cursor[e], 1);
        int slot = g_offsets[e] + pos;
        g_slot_token[slot] = t;
        g_slot_w[slot] = g_top_w[t*2+j];
        g_slot_of[t*2+j] = slot;
    }
}

__global__ void final_add_kernel(float* __restrict__ out) {
    int t = blockIdx.x;
    int s0 = g_slot_of[t*2], s1 = g_slot_of[t*2+1];
    float w0 = g_slot_w[s0], w1 = g_slot_w[s1];
    for (int i = threadIdx.x*4; i < Dm; i += 256*4) {
        float4 a  = *(float4*)(out + (size_t)t*Dm + i);
        float4 y0 = *(const float4*)(g_y + (size_t)s0*Dm + i);
        float4 y1 = *(const float4*)(g_y + (size_t)s1*Dm + i);
        a.x += w0*y0.x + w1*y1.x;
        a.y += w0*y0.y + w1*y1.y;
        a.z += w0*y0.z + w1*y1.z;
        a.w += w0*y0.w + w1*y1.w;
        *(float4*)(out + (size_t)t*Dm + i) = a;
    }
}

// ---------------- launch ----------------
extern "C" void kernel_launch(void* const* d_in, const int* in_sizes, int n_in,
                              void* d_out, int out_size) {
    const float* x           = (const float*)d_in[0];
    const float* w_q         = (const float*)d_in[1];
    const float* w_k         = (const float*)d_in[2];
    const float* w_v         = (const float*)d_in[3];
    const float* w_o         = (const float*)d_in[4];
    const float* attn_norm_w = (const float*)d_in[5];
    const float* moe_norm_w  = (const float*)d_in[6];
    const float* gate_w      = (const float*)d_in[7];
    const float* w1          = (const float*)d_in[8];
    const float* w3          = (const float*)d_in[9];
    const float* w2          = (const float*)d_in[10];
    float* out = (float*)d_out;

    float *ph, *pq, *pk, *pv, *pao, *pg, *py;
    float *pwq, *pwk, *pwv, *pwo;
    cudaGetSymbolAddress((void**)&ph,  g_h);
    cudaGetSymbolAddress((void**)&pq,  g_q);
    cudaGetSymbolAddress((void**)&pk,  g_k);
    cudaGetSymbolAddress((void**)&pv,  g_v);
    cudaGetSymbolAddress((void**)&pao, g_ao);
    cudaGetSymbolAddress((void**)&pg,  g_g);
    cudaGetSymbolAddress((void**)&py,  g_y);
    cudaGetSymbolAddress((void**)&pwq, r_wq);
    cudaGetSymbolAddress((void**)&pwk, r_wk);
    cudaGetSymbolAddress((void**)&pwv, r_wv);
    cudaGetSymbolAddress((void**)&pwo, r_wo);

    static int attr_set = 0;
    const int attn_smem = AT_SMEM_WORDS * 4;
    if (!attr_set) {
        cudaFuncSetAttribute(attn_mma_kernel,
                             cudaFuncAttributeMaxDynamicSharedMemorySize, attn_smem);
        cudaFuncSetAttribute(tf32_gemm,
                             cudaFuncAttributeMaxDynamicSharedMemorySize, GEMM_SMEM);
        cudaFuncSetAttribute(moe13_gemm,
                             cudaFuncAttributeMaxDynamicSharedMemorySize, MOE_SMEM);
        attr_set = 1;
    }

    roundcopy<<<(Dm*Dm/4 + 255)/256, 256>>>(w_q, pwq, Dm*Dm/4);
    roundcopy<<<(Dm*KVD/4 + 255)/256, 256>>>(w_k, pwk, Dm*KVD/4);
    roundcopy<<<(Dm*KVD/4 + 255)/256, 256>>>(w_v, pwv, Dm*KVD/4);
    roundcopy<<<(Dm*Dm/4 + 255)/256, 256>>>(w_o, pwo, Dm*Dm/4);

    zero_kernel<<<1, 32>>>();
    rmsnorm_kernel<<<Ttok, 256>>>(x, attn_norm_w, ph);
    tf32_gemm<<<dim3(Dm/128, Ttok/128, 1), 256, GEMM_SMEM>>>(ph, pwq, pq, Ttok, Dm, Dm,
                                                  nullptr, 0, nullptr, nullptr);
    tf32_gemm<<<dim3(KVD/128, Ttok/128, 2), 256, GEMM_SMEM>>>(ph, pwk, pk, Ttok, KVD, Dm,
                                                   nullptr, 0, pwv, pv);
    {
        int tot = Ttok*NH*(HDv/2) + Ttok*KVHv*(HDv/2) + Ttok*(KVD/2);
        rope_kernel<<<(tot + 255)/256, 256>>>();
    }
    attn_mma_kernel<<<dim3(Lq/64, NH, Bq), 128, attn_smem>>>();
    tf32_gemm<<<dim3(Dm/128, Ttok/128, 1), 256, GEMM_SMEM>>>(pao, pwo, out, Ttok, Dm, Dm,
                                                  x, 0, nullptr, nullptr);
    rmsnorm_kernel<<<Ttok, 256>>>(out, moe_norm_w, ph);
    gate_kernel<<<Ttok, 256>>>(gate_w);
    finalize_gate_kernel<<<1, 256>>>(out + (size_t)Ttok*Dm);
    scatter_kernel<<<(Ttok + 255)/256, 256>>>();
    moe13_gemm<<<dim3(NI/64, SLOTS/128, NE), 256, MOE_SMEM>>>(w1, w3);
    tf32_gemm<<<dim3(Dm/128, SLOTS/128, NE), 256, GEMM_SMEM>>>(pg, w2, py, 0, Dm, NI,
                                                    nullptr, 2, nullptr, nullptr);
    final_add_kernel<<<Ttok, 256>>>(out);
}

// round 16
// speedup vs baseline: 1.0282x; 1.0023x over previous
#include <cuda_runtime.h>
#include <math.h>

#define Bq 2
#define Lq 2048
#define Dm 2048
#define NH 16
#define HDv 128
#define KVHv 4
#define NE 8
#define NI 1024
#define Ttok (Bq*Lq)          /* 4096 */
#define KVD (KVHv*HDv)        /* 512  */
#define SLOTS (Ttok*2)        /* 8192 */

// ---------------- scratch ----------------
__device__ float g_h[Ttok*Dm];
__device__ float g_q[Ttok*Dm];
__device__ float g_k[Ttok*KVD];
__device__ float g_v[Ttok*KVD];
__device__ float g_ao[Ttok*Dm];
__device__ float g_g[SLOTS*NI];
__device__ float g_scores[Ttok*NE];
__device__ int   g_counts[NE];
__device__ int   g_offsets[NE+1];
__device__ int   g_cursor[NE];
__device__ int   g_top_idx[Ttok*2];
__device__ float g_top_w[Ttok*2];
__device__ int   g_slot_token[SLOTS];
__device__ float g_slot_w[SLOTS];
__device__ float r_wq[Dm*Dm];
__device__ float r_wk[Dm*KVD];
__device__ float r_wv[Dm*KVD];
__device__ float r_wo[Dm*Dm];

__device__ __forceinline__ unsigned f2tf(float x) {
    unsigned r; asm("cvt.rna.tf32.f32 %0, %1;" : "=r"(r) : "f"(x)); return r;
}
__device__ __forceinline__ float f2tff(float x) { return __uint_as_float(f2tf(x)); }
__device__ __forceinline__ void cp16(unsigned d, const void* s) {
    asm volatile("cp.async.cg.shared.global [%0], [%1], 16;" :: "r"(d), "l"(s));
}
__device__ __forceinline__ void cp_commit() {
    asm volatile("cp.async.commit_group;");
}
template<int N> __device__ __forceinline__ void cp_wait() {
    asm volatile("cp.async.wait_group %0;" :: "n"(N));
}
#define MMA_TF32(d0,d1,d2,d3,a0,a1,a2,a3,b0,b1) \
    asm volatile( \
        "mma.sync.aligned.m16n8k8.row.col.f32.tf32.tf32.f32 " \
        "{%0,%1,%2,%3}, {%4,%5,%6,%7}, {%8,%9}, {%0,%1,%2,%3};" \
        : "+f"(d0), "+f"(d1), "+f"(d2), "+f"(d3) \
        : "r"(a0), "r"(a1), "r"(a2), "r"(a3), "r"(b0), "r"(b1))

// ---------------- small kernels ----------------
__global__ void zero_kernel() {
    int i = threadIdx.x;
    if (i < NE) { g_counts[i] = 0; g_cursor[i] = 0; }
}

__global__ void roundcopy(const float* __restrict__ s, float* __restrict__ d, int n4) {
    int i = blockIdx.x*256 + threadIdx.x;
    if (i >= n4) return;
    float4 v = ((const float4*)s)[i];
    uint4 u;
    u.x = f2tf(v.x); u.y = f2tf(v.y); u.z = f2tf(v.z); u.w = f2tf(v.w);
    ((uint4*)d)[i] = u;
}

__global__ void rmsnorm_kernel(const float* __restrict__ in,
                               const float* __restrict__ w,
                               float* __restrict__ out) {
    int t = blockIdx.x;
    const float* row = in + (size_t)t*Dm;
    float ss = 0.f;
    for (int i = threadIdx.x; i < Dm; i += 256) { float v = row[i]; ss += v*v; }
    __shared__ float red[8];
    for (int o = 16; o; o >>= 1) ss += __shfl_xor_sync(0xffffffffu, ss, o);
    if ((threadIdx.x & 31) == 0) red[threadIdx.x >> 5] = ss;
    __syncthreads();
    float tot = 0.f;
    #pragma unroll
    for (int i = 0; i < 8; i++) tot += red[i];
    float inv = rsqrtf(tot * (1.f/(float)Dm) + 1e-5f);
    for (int i = threadIdx.x; i < Dm; i += 256)
        out[(size_t)t*Dm + i] = f2tff(row[i] * inv * w[i]);
}

// ---------------- tf32 GEMM, cp.async 2-stage, single barrier per k-tile ----------------
// mode 0: plain (z==1 selects B2/C2). mode 1: gather rows via slot_token.
// mode 2: contiguous grouped rows, plain store.
// mode 3: contiguous grouped rows, epilogue = atomicAdd(out[token], slot_w * val).
#define GA_STRIDE 36
#define GB_STRIDE 136
#define GA_BUF (128*GA_STRIDE)
#define GB_BUF (32*GB_STRIDE)
#define GEMM_SMEM ((2*GA_BUF + 2*GB_BUF)*4)

__global__ void __launch_bounds__(256, 2) tf32_gemm(
    const float* __restrict__ A, const float* __restrict__ B,
    float* __restrict__ C, int M, int N, int K,
    const float* __restrict__ addsrc, int mode,
    const float* __restrict__ B2, float* __restrict__ C2)
{
    extern __shared__ float dsm[];
    float* As = dsm;
    float* Bs = dsm + 2*GA_BUF;
    int cnt, off;
    if (mode == 0) {
        cnt = M; off = 0;
        if (blockIdx.z == 1) { B = B2; C = C2; }
    } else {
        int e = blockIdx.z;
        cnt = g_counts[e]; off = g_offsets[e];
        B += (size_t)e * K * N;
    }
    int bm = blockIdx.y * 128;
    if (bm >= cnt) return;
    int bn = blockIdx.x * 128;
    int tid = threadIdx.x;
    int lane = tid & 31, wid = tid >> 5;
    int warp_m = wid >> 2, warp_n = wid & 3;
    int lq = lane >> 2, lr = lane & 3;

    const float* aptr[4];
    #pragma unroll
    for (int r = 0; r < 4; r++) {
        int row = bm + r*32 + (tid >> 3);
        int re = row < cnt ? row : cnt - 1;
        if (mode == 1)      aptr[r] = g_h + (size_t)g_slot_token[off + re] * K;
        else if (mode >= 2) aptr[r] = A + (size_t)(off + re) * K;
        else                aptr[r] = A + (size_t)re * K;
    }
    int ak4 = (tid & 7) * 4;
    int bk  = tid >> 5;
    int bn4 = lane * 4;
    const float* bsrc = B + (size_t)bk*N + bn + bn4;

    unsigned as_sm = (unsigned)__cvta_generic_to_shared(As);
    unsigned bs_sm = (unsigned)__cvta_generic_to_shared(Bs);
    unsigned a_dst0 = as_sm + (((tid>>3)*GA_STRIDE) + ak4)*4u;
    unsigned b_dst0 = bs_sm + ((bk*GB_STRIDE) + bn4)*4u;

    float acc[4][4][4];
    #pragma unroll
    for (int i=0;i<4;i++)
        #pragma unroll
        for(int j=0;j<4;j++)
            #pragma unroll
            for(int c=0;c<4;c++) acc[i][j][c]=0.f;

    int nkt = K >> 5;
    #pragma unroll
    for (int r = 0; r < 4; r++)
        cp16(a_dst0 + (unsigned)(r*32*GA_STRIDE)*4u, aptr[r] + ak4);
    #pragma unroll
    for (int r = 0; r < 4; r++)
        cp16(b_dst0 + (unsigned)(r*8*GB_STRIDE)*4u, bsrc + (size_t)(r*8)*N);
    cp_commit();

    for (int it = 0; it < nkt; it++) {
        int cur = it & 1;
        cp_wait<0>();
        __syncthreads();
        if (it + 1 < nkt) {
            int nb = (it + 1) & 1;
            int k0 = (it + 1) << 5;
            unsigned ad = a_dst0 + (unsigned)(nb*GA_BUF)*4u;
            unsigned bd = b_dst0 + (unsigned)(nb*GB_BUF)*4u;
            #pragma unroll
            for (int r = 0; r < 4; r++)
                cp16(ad + (unsigned)(r*32*GA_STRIDE)*4u, aptr[r] + k0 + ak4);
            #pragma unroll
            for (int r = 0; r < 4; r++)
                cp16(bd + (unsigned)(r*8*GB_STRIDE)*4u, bsrc + (size_t)(k0 + r*8)*N);
            cp_commit();
        }
        const float* Ac = As + cur*GA_BUF;
        const float* Bc = Bs + cur*GB_BUF;
        #pragma unroll
        for (int ks = 0; ks < 4; ks++) {
            int k8 = ks*8;
            unsigned af[4][4], bf[4][2];
            #pragma unroll
            for (int mt=0; mt<4; mt++) {
                int m0 = warp_m*64 + mt*16;
                const float* p = &Ac[(m0+lq)*GA_STRIDE + k8 + lr];
                af[mt][0] = __float_as_uint(p[0]);
                af[mt][1] = __float_as_uint(p[8*GA_STRIDE]);
                af[mt][2] = __float_as_uint(p[4]);
                af[mt][3] = __float_as_uint(p[8*GA_STRIDE+4]);
            }
            #pragma unroll
            for (int nt=0; nt<4; nt++) {
                int n0 = warp_n*32 + nt*8 + lq;
                bf[nt][0] = __float_as_uint(Bc[(k8+lr)*GB_STRIDE + n0]);
                bf[nt][1] = __float_as_uint(Bc[(k8+4+lr)*GB_STRIDE + n0]);
            }
            #pragma unroll
            for (int mt=0; mt<4; mt++)
                #pragma unroll
                for (int nt=0; nt<4; nt++)
                    MMA_TF32(acc[mt][nt][0], acc[mt][nt][1], acc[mt][nt][2], acc[mt][nt][3],
                             af[mt][0], af[mt][1], af[mt][2], af[mt][3],
                             bf[nt][0], bf[nt][1]);
        }
    }
    #pragma unroll
    for (int mt=0; mt<4; mt++) {
        int row0 = bm + warp_m*64 + mt*16 + lq;
        #pragma unroll
        for (int half=0; half<2; half++) {
            int row = row0 + half*8;
            if (row >= cnt) continue;
            size_t crow = (size_t)(off + row);
            if (mode == 3) {
                int tok = g_slot_token[crow];
                float wgt = g_slot_w[crow];
                float* orow = C + (size_t)tok*N;
                #pragma unroll
                for (int nt=0; nt<4; nt++) {
                    int col = bn + warp_n*32 + nt*8 + 2*lr;
                    atomicAdd(orow + col,     wgt*acc[mt][nt][half*2+0]);
                    atomicAdd(orow + col + 1, wgt*acc[mt][nt][half*2+1]);
                }
            } else {
                #pragma unroll
                for (int nt=0; nt<4; nt++) {
                    int col = bn + warp_n*32 + nt*8 + 2*lr;
                    float2 v;
                    v.x = acc[mt][nt][half*2+0];
                    v.y = acc[mt][nt][half*2+1];
                    if (addsrc) {
                        float2 s = *(const float2*)(addsrc + crow*N + col);
                        v.x += s.x; v.y += s.y;
                    }
                    *(float2*)(C + crow*N + col) = v;
                }
            }
        }
    }
}

// ---------------- fused MoE up-proj, single barrier per k-tile ----------------
#define MA_STRIDE 36
#define MB_STRIDE 72
#define MA_BUF (128*MA_STRIDE)
#define MB_BUF (32*MB_STRIDE)
#define MOE_STAGE (MA_BUF + 2*MB_BUF)
#define MOE_SMEM (2*MOE_STAGE*4)

__global__ void __launch_bounds__(256, 2) moe13_gemm(
    const float* __restrict__ W1, const float* __restrict__ W3)
{
    extern __shared__ float dsm[];
    int e = blockIdx.z;
    int cnt = g_counts[e], off = g_offsets[e];
    int bm = blockIdx.y * 128;
    if (bm >= cnt) return;
    int bn = blockIdx.x * 64;
    int tid = threadIdx.x;
    int lane = tid & 31, wid = tid >> 5;
    int warp_m = wid >> 1, warp_n = wid & 1;
    int lq = lane >> 2, lr = lane & 3;

    const float* W1e = W1 + (size_t)e*Dm*NI;
    const float* W3e = W3 + (size_t)e*Dm*NI;

    const float* aptr[4];
    #pragma unroll
    for (int r = 0; r < 4; r++) {
        int row = bm + r*32 + (tid >> 3);
        int re = row < cnt ? row : cnt - 1;
        aptr[r] = g_h + (size_t)g_slot_token[off + re] * Dm;
    }
    int ak4 = (tid & 7) * 4;
    int brow = tid >> 4;
    int bc4  = (tid & 15) * 4;
    const float* b1src = W1e + (size_t)brow*NI + bn + bc4;
    const float* b3src = W3e + (size_t)brow*NI + bn + bc4;

    unsigned sm0 = (unsigned)__cvta_generic_to_shared(dsm);
    unsigned a_dst0  = sm0 + (((tid>>3)*MA_STRIDE) + ak4)*4u;
    unsigned b1_dst0 = sm0 + (unsigned)(MA_BUF + brow*MB_STRIDE + bc4)*4u;
    unsigned b3_dst0 = b1_dst0 + (unsigned)(MB_BUF)*4u;

    float acc1[2][4][4], acc3[2][4][4];
    #pragma unroll
    for (int i=0;i<2;i++)
        #pragma unroll
        for(int j=0;j<4;j++)
            #pragma unroll
            for(int c=0;c<4;c++){acc1[i][j][c]=0.f;acc3[i][j][c]=0.f;}

    const int nkt = Dm >> 5;
    #pragma unroll
    for (int r = 0; r < 4; r++)
        cp16(a_dst0 + (unsigned)(r*32*MA_STRIDE)*4u, aptr[r] + ak4);
    #pragma unroll
    for (int r = 0; r < 2; r++) {
        cp16(b1_dst0 + (unsigned)(r*16*MB_STRIDE)*4u, b1src + (size_t)(r*16)*NI);
        cp16(b3_dst0 + (unsigned)(r*16*MB_STRIDE)*4u, b3src + (size_t)(r*16)*NI);
    }
    cp_commit();

    for (int it = 0; it < nkt; it++) {
        int cur = it & 1;
        cp_wait<0>();
        __syncthreads();
        if (it + 1 < nkt) {
            int nb = (it + 1) & 1;
            int k0 = (it + 1) << 5;
            unsigned ad  = a_dst0  + (unsigned)(nb*MOE_STAGE)*4u;
            unsigned b1d = b1_dst0 + (unsigned)(nb*MOE_STAGE)*4u;
            unsigned b3d = b3_dst0 + (unsigned)(nb*MOE_STAGE)*4u;
            #pragma unroll
            for (int r = 0; r < 4; r++)
                cp16(ad + (unsigned)(r*32*MA_STRIDE)*4u, aptr[r] + k0 + ak4);
            #pragma unroll
            for (int r = 0; r < 2; r++) {
                cp16(b1d + (unsigned)(r*16*MB_STRIDE)*4u, b1src + (size_t)(k0 + r*16)*NI);
                cp16(b3d + (unsigned)(r*16*MB_STRIDE)*4u, b3src + (size_t)(k0 + r*16)*NI);
            }
            cp_commit();
        }
        const float* Ac  = dsm + cur*MOE_STAGE;
        const float* B1c = Ac + MA_BUF;
        const float* B3c = B1c + MB_BUF;
        #pragma unroll
        for (int ks = 0; ks < 4; ks++) {
            int k8 = ks*8;
            unsigned af[2][4], b1f[4][2], b3f[4][2];
            #pragma unroll
            for (int mt=0; mt<2; mt++) {
                int m0 = warp_m*32 + mt*16;
                const float* p = &Ac[(m0+lq)*MA_STRIDE + k8 + lr];
                af[mt][0] = __float_as_uint(p[0]);
                af[mt][1] = __float_as_uint(p[8*MA_STRIDE]);
                af[mt][2] = __float_as_uint(p[4]);
                af[mt][3] = __float_as_uint(p[8*MA_STRIDE+4]);
            }
            #pragma unroll
            for (int nt=0; nt<4; nt++) {
                int n0 = warp_n*32 + nt*8 + lq;
                b1f[nt][0] = __float_as_uint(B1c[(k8+lr)*MB_STRIDE + n0]);
                b1f[nt][1] = __float_as_uint(B1c[(k8+4+lr)*MB_STRIDE + n0]);
                b3f[nt][0] = __float_as_uint(B3c[(k8+lr)*MB_STRIDE + n0]);
                b3f[nt][1] = __float_as_uint(B3c[(k8+4+lr)*MB_STRIDE + n0]);
            }
            #pragma unroll
            for (int mt=0; mt<2; mt++)
                #pragma unroll
                for (int nt=0; nt<4; nt++) {
                    MMA_TF32(acc1[mt][nt][0], acc1[mt][nt][1], acc1[mt][nt][2], acc1[mt][nt][3],
                             af[mt][0], af[mt][1], af[mt][2], af[mt][3],
                             b1f[nt][0], b1f[nt][1]);
                    MMA_TF32(acc3[mt][nt][0], acc3[mt][nt][1], acc3[mt][nt][2], acc3[mt][nt][3],
                             af[mt][0], af[mt][1], af[mt][2], af[mt][3],
                             b3f[nt][0], b3f[nt][1]);
                }
        }
    }
    #pragma unroll
    for (int mt=0; mt<2; mt++) {
        int row0 = bm + warp_m*32 + mt*16 + lq;
        #pragma unroll
        for (int half=0; half<2; half++) {
            int row = row0 + half*8;
            if (row >= cnt) continue;
            size_t crow = (size_t)(off + row);
            #pragma unroll
            for (int nt=0; nt<4; nt++) {
                int col = bn + warp_n*32 + nt*8 + 2*lr;
                float gg0 = acc1[mt][nt][half*2+0], uu0 = acc3[mt][nt][half*2+0];
                float gg1 = acc1[mt][nt][half*2+1], uu1 = acc3[mt][nt][half*2+1];
                float2 v;
                v.x = f2tff(gg0 / (1.f + __expf(-gg0)) * uu0);
                v.y = f2tff(gg1 / (1.f + __expf(-gg1)) * uu1);
                *(float2*)(g_g + crow*NI + col) = v;
            }
        }
    }
}

// ---------------- RoPE (rounds q,k; also rounds v) ----------------
__global__ void rope_kernel() {
    int idx = blockIdx.x*256 + threadIdx.x;
    const int totq = Ttok*NH*(HDv/2);
    const int totk = totq + Ttok*KVHv*(HDv/2);
    const int tot  = totk + Ttok*(KVD/2);
    if (idx >= tot) return;
    if (idx >= totk) {
        int id2 = idx - totk;
        float* p = g_v + (size_t)id2*2;
        p[0] = f2tff(p[0]); p[1] = f2tff(p[1]);
        return;
    }
    float* base; int t, i;
    if (idx < totq) {
        i = idx & 63;
        int hh = (idx >> 6) & (NH-1);
        t = idx >> 10;
        base = g_q + (size_t)t*Dm + hh*HDv + 2*i;
    } else {
        int id2 = idx - totq;
        i = id2 & 63;
        int hh = (id2 >> 6) & (KVHv-1);
        t = id2 >> 8;
        base = g_k + (size_t)t*KVD + hh*HDv + 2*i;
    }
    int pos = t & (Lq-1);
    float inv = exp2f(-(float)i * (13.287712379549449f/64.f));
    float ang = (float)pos * inv;
    float c = cosf(ang), s = sinf(ang);
    float xr = base[0], xi = base[1];
    base[0] = f2tff(xr*c - xi*s);
    base[1] = f2tff(xr*s + xi*c);
}

// ---------------- flash attention: 64-row Q blocks, 3-stage K/V, 2 CTAs/SM ----------------
#define QPAD 132
#define VPAD 136
#define PPAD 36
#define AT_KS 0
#define AT_KBUF (32*QPAD)
#define AT_VS (3*AT_KBUF)
#define AT_VBUF (32*VPAD)
#define AT_PS (AT_VS + 3*AT_VBUF)
#define AT_QS AT_KBUF
#define AT_SMEM_WORDS (AT_PS + 64*PPAD)

__global__ void __launch_bounds__(128, 2) attn_mma_kernel() {
    extern __shared__ float sm[];
    int b = blockIdx.z, h = blockIdx.y;
    int q0 = blockIdx.x * 64;
    int kvh = h >> 2;
    int tid = threadIdx.x;
    int lane = tid & 31, w = tid >> 5;
    int lq = lane >> 2, lr = lane & 3;
    const float scale = 0.08838834764831845f;

    unsigned sm_base = (unsigned)__cvta_generic_to_shared(sm);
    int ntiles = (q0 + 64) / 32;

    for (int idx = tid; idx < 32*32; idx += 128) {
        int row = idx >> 5, c4 = (idx & 31) * 4;
        size_t goff = (size_t)(b*Lq + row)*KVD + kvh*HDv + c4;
        cp16(sm_base + (unsigned)(AT_KS + row*QPAD + c4)*4u, g_k + goff);
        cp16(sm_base + (unsigned)(AT_VS + row*VPAD + c4)*4u, g_v + goff);
    }
    cp_commit();

    for (int idx = tid; idx < 64*32; idx += 128) {
        int row = idx >> 5, c4 = (idx & 31) * 4;
        float4 qv = *(const float4*)(g_q + (size_t)(b*Lq + q0 + row)*Dm + h*HDv + c4);
        *(float4*)&sm[AT_QS + row*QPAD + c4] = qv;
    }
    __syncthreads();
    unsigned qf[16][4];
    #pragma unroll
    for (int ks = 0; ks < 16; ks++) {
        int k8 = ks*8;
        const float* qp = &sm[AT_QS + (w*16+lq)*QPAD + k8 + lr];
        qf[ks][0] = __float_as_uint(qp[0]);
        qf[ks][1] = __float_as_uint(qp[8*QPAD]);
        qf[ks][2] = __float_as_uint(qp[4]);
        qf[ks][3] = __float_as_uint(qp[8*QPAD+4]);
    }
    __syncthreads();

    if (ntiles > 1) {
        for (int idx = tid; idx < 32*32; idx += 128) {
            int row = idx >> 5, c4 = (idx & 31) * 4;
            size_t goff = (size_t)(b*Lq + 32 + row)*KVD + kvh*HDv + c4;
            cp16(sm_base + (unsigned)(AT_KS + AT_KBUF + row*QPAD + c4)*4u, g_k + goff);
            cp16(sm_base + (unsigned)(AT_VS + AT_VBUF + row*VPAD + c4)*4u, g_v + goff);
        }
        cp_commit();
    }

    float o[16][4];
    #pragma unroll
    for (int nt=0;nt<16;nt++){o[nt][0]=0.f;o[nt][1]=0.f;o[nt][2]=0.f;o[nt][3]=0.f;}
    float m0 = -1e30f, m1 = -1e30f, l0 = 0.f, l1 = 0.f;
    int row_base = q0 + w*16;

    for (int kt = 0; kt < ntiles; kt++) {
        if (kt + 1 < ntiles) cp_wait<1>(); else cp_wait<0>();
        __syncthreads();
        if (kt + 2 < ntiles) {
            int nb = (kt + 2) % 3;
            int nbase = (kt + 2) * 32;
            for (int idx = tid; idx < 32*32; idx += 128) {
                int row = idx >> 5, c4 = (idx & 31) * 4;
                size_t goff = (size_t)(b*Lq + nbase + row)*KVD + kvh*HDv + c4;
                cp16(sm_base + (unsigned)(AT_KS + nb*AT_KBUF + row*QPAD + c4)*4u, g_k + goff);
                cp16(sm_base + (unsigned)(AT_VS + nb*AT_VBUF + row*VPAD + c4)*4u, g_v + goff);
            }
            cp_commit();
        }
        int cur = kt % 3;
        int base = kt * 32;
        const float* Kc = sm + AT_KS + cur*AT_KBUF;
        const float* Vc = sm + AT_VS + cur*AT_VBUF;

        if (base <= row_base + 15) {
            float s[4][4];
            #pragma unroll
            for (int nt=0;nt<4;nt++){s[nt][0]=0.f;s[nt][1]=0.f;s[nt][2]=0.f;s[nt][3]=0.f;}
            #pragma unroll
            for (int ks = 0; ks < 16; ks++) {
                int k8 = ks*8;
                #pragma unroll
                for (int nt=0; nt<4; nt++) {
                    unsigned b0 = __float_as_uint(Kc[(nt*8+lq)*QPAD + k8 + lr]);
                    unsigned b1 = __float_as_uint(Kc[(nt*8+lq)*QPAD + k8 + lr + 4]);
                    MMA_TF32(s[nt][0], s[nt][1], s[nt][2], s[nt][3],
                             qf[ks][0], qf[ks][1], qf[ks][2], qf[ks][3], b0, b1);
                }
            }
            #pragma unroll
            for (int nt=0; nt<4; nt++) {
                s[nt][0]*=scale; s[nt][1]*=scale; s[nt][2]*=scale; s[nt][3]*=scale;
            }

            if (base + 31 > row_base) {
                int i0 = row_base + lq, i1 = row_base + lq + 8;
                #pragma unroll
                for (int nt=0; nt<4; nt++) {
                    int j = base + nt*8 + 2*lr;
                    if (j   > i0) s[nt][0] = -1e30f;
                    if (j+1 > i0) s[nt][1] = -1e30f;
                    if (j   > i1) s[nt][2] = -1e30f;
                    if (j+1 > i1) s[nt][3] = -1e30f;
                }
            }

            float mx0 = -1e30f, mx1 = -1e30f;
            #pragma unroll
            for (int nt=0; nt<4; nt++) {
                mx0 = fmaxf(mx0, fmaxf(s[nt][0], s[nt][1]));
                mx1 = fmaxf(mx1, fmaxf(s[nt][2], s[nt][3]));
            }
            mx0 = fmaxf(mx0, __shfl_xor_sync(0xffffffffu, mx0, 1));
            mx0 = fmaxf(mx0, __shfl_xor_sync(0xffffffffu, mx0, 2));
            mx1 = fmaxf(mx1, __shfl_xor_sync(0xffffffffu, mx1, 1));
            mx1 = fmaxf(mx1, __shfl_xor_sync(0xffffffffu, mx1, 2));
            float mn0 = fmaxf(m0, mx0), mn1 = fmaxf(m1, mx1);
            float al0 = __expf(m0 - mn0), al1 = __expf(m1 - mn1);
            float rs0 = 0.f, rs1 = 0.f;
            #pragma unroll
            for (int nt=0; nt<4; nt++) {
                s[nt][0] = __expf(s[nt][0] - mn0);
                s[nt][1] = __expf(s[nt][1] - mn0);
                s[nt][2] = __expf(s[nt][2] - mn1);
                s[nt][3] = __expf(s[nt][3] - mn1);
                rs0 += s[nt][0] + s[nt][1];
                rs1 += s[nt][2] + s[nt][3];
            }
            rs0 += __shfl_xor_sync(0xffffffffu, rs0, 1);
            rs0 += __shfl_xor_sync(0xffffffffu, rs0, 2);
            rs1 += __shfl_xor_sync(0xffffffffu, rs1, 1);
            rs1 += __shfl_xor_sync(0xffffffffu, rs1, 2);
            l0 = l0*al0 + rs0;
            l1 = l1*al1 + rs1;
            m0 = mn0; m1 = mn1;
            #pragma unroll
            for (int nt=0; nt<16; nt++) {
                o[nt][0]*=al0; o[nt][1]*=al0; o[nt][2]*=al1; o[nt][3]*=al1;
            }

            #pragma unroll
            for (int nt=0; nt<4; nt++) {
                float* p0 = &sm[AT_PS + (w*16+lq)*PPAD + nt*8 + 2*lr];
                p0[0] = __uint_as_float(f2tf(s[nt][0]));
                p0[1] = __uint_as_float(f2tf(s[nt][1]));
                float* p1 = &sm[AT_PS + (w*16+lq+8)*PPAD + nt*8 + 2*lr];
                p1[0] = __uint_as_float(f2tf(s[nt][2]));
                p1[1] = __uint_as_float(f2tf(s[nt][3]));
            }
            __syncwarp();

            #pragma unroll
            for (int ks = 0; ks < 4; ks++) {
                int k8 = ks*8;
                const float* pp = &sm[AT_PS + (w*16+lq)*PPAD + k8 + lr];
                unsigned a0 = __float_as_uint(pp[0]);
                unsigned a1 = __float_as_uint(pp[8*PPAD]);
                unsigned a2 = __float_as_uint(pp[4]);
                unsigned a3 = __float_as_uint(pp[8*PPAD+4]);
                #pragma unroll
                for (int nt=0; nt<16; nt++) {
                    unsigned b0 = __float_as_uint(Vc[(k8+lr)*VPAD + nt*8 + lq]);
                    unsigned b1 = __float_as_uint(Vc[(k8+lr+4)*VPAD + nt*8 + lq]);
                    MMA_TF32(o[nt][0], o[nt][1], o[nt][2], o[nt][3],
                             a0, a1, a2, a3, b0, b1);
                }
            }
        }
    }

    float inv0 = 1.f / l0, inv1 = 1.f / l1;
    int t0 = b*Lq + row_base + lq;
    #pragma unroll
    for (int nt=0; nt<16; nt++) {
        int col = h*HDv + nt*8 + 2*lr;
        float2 v0 = make_float2(f2tff(o[nt][0]*inv0), f2tff(o[nt][1]*inv0));
        float2 v1 = make_float2(f2tff(o[nt][2]*inv1), f2tff(o[nt][3]*inv1));
        *(float2*)(g_ao + (size_t)t0*Dm + col) = v0;
        *(float2*)(g_ao + (size_t)(t0+8)*Dm + col) = v1;
    }
}

// ---------------- gating ----------------
__global__ void gate_kernel(const float* __restrict__ gw) {
    int t = blockIdx.x;
    int warp = threadIdx.x >> 5, lane = threadIdx.x & 31;
    const float* row = g_h + (size_t)t*Dm;
    float s = 0.f;
    for (int i = lane; i < Dm; i += 32) s += row[i] * gw[(size_t)i*NE + warp];
    for (int o = 16; o; o >>= 1) s += __shfl_xor_sync(0xffffffffu, s, o);
    __shared__ float logits[NE];
    if (lane == 0) logits[warp] = s;
    __syncthreads();
    if (threadIdx.x == 0) {
        float mx = logits[0];
        for (int e = 1; e < NE; e++) mx = fmaxf(mx, logits[e]);
        float ex[NE]; float sum = 0.f;
        for (int e = 0; e < NE; e++) { ex[e] = expf(logits[e]-mx); sum += ex[e]; }
        float invs = 1.f/sum;
        float sc[NE];
        for (int e = 0; e < NE; e++) { sc[e] = ex[e]*invs; g_scores[t*NE+e] = sc[e]; }
        int e0 = 0; float m0 = sc[0];
        for (int e = 1; e < NE; e++) if (sc[e] > m0) { m0 = sc[e]; e0 = e; }
        int e1 = -1; float m1 = -1.f;
        for (int e = 0; e < NE; e++) if (e != e0 && sc[e] > m1) { m1 = sc[e]; e1 = e; }
        float wsum = m0 + m1;
        g_top_idx[t*2]   = e0;  g_top_idx[t*2+1] = e1;
        g_top_w[t*2]     = m0/wsum;
        g_top_w[t*2+1]   = m1/wsum;
        atomicAdd(&g_counts[e0], 1);
        atomicAdd(&g_counts[e1], 1);
    }
}

__global__ void finalize_gate_kernel(float* aux_out) {
    int warp = threadIdx.x >> 5, lane = threadIdx.x & 31;
    float s = 0.f;
    for (int t = lane; t < Ttok; t += 32) s += g_scores[t*NE + warp];
    for (int o = 16; o; o >>= 1) s += __shfl_xor_sync(0xffffffffu, s, o);
    __shared__ float ps[NE];
    if (lane == 0) ps[warp] = s;
    __syncthreads();
    if (threadIdx.x == 0) {
        int off = 0; float aux = 0.f;
        for (int e = 0; e < NE; e++) {
            g_offsets[e] = off; off += g_counts[e];
            float f = (float)g_counts[e] / (float)Ttok;
            float p = ps[e] / (float)Ttok;
            aux += f * p;
        }
        g_offsets[NE] = off;
        aux_out[0] = 0.01f * (float)NE * aux;
    }
}

__global__ void scatter_kernel() {
    int t = blockIdx.x*256 + threadIdx.x;
    if (t >= Ttok) return;
    for (int j = 0; j < 2; j++) {
        int e = g_top_idx[t*2+j];
        int pos = atomicAdd(&g_cursor[e], 1);
        int slot = g_offsets[e] + pos;
        g_slot_token[slot] = t;
        g_slot_w[slot] = g_top_w[t*2+j];
    }
}

// ---------------- launch ----------------
extern "C" void kernel_launch(void* const* d_in, const int* in_sizes, int n_in,
                              void* d_out, int out_size) {
    const float* x           = (const float*)d_in[0];
    const float* w_q         = (const float*)d_in[1];
    const float* w_k         = (const float*)d_in[2];
    const float* w_v         = (const float*)d_in[3];
    const float* w_o         = (const float*)d_in[4];
    const float* attn_norm_w = (const float*)d_in[5];
    const float* moe_norm_w  = (const float*)d_in[6];
    const float* gate_w      = (const float*)d_in[7];
    const float* w1          = (const float*)d_in[8];
    const float* w3          = (const float*)d_in[9];
    const float* w2          = (const float*)d_in[10];
    float* out = (float*)d_out;

    float *ph, *pq, *pk, *pv, *pao, *pg;
    float *pwq, *pwk, *pwv, *pwo;
    cudaGetSymbolAddress((void**)&ph,  g_h);
    cudaGetSymbolAddress((void**)&pq,  g_q);
    cudaGetSymbolAddress((void**)&pk,  g_k);
    cudaGetSymbolAddress((void**)&pv,  g_v);
    cudaGetSymbolAddress((void**)&pao, g_ao);
    cudaGetSymbolAddress((void**)&pg,  g_g);
    cudaGetSymbolAddress((void**)&pwq, r_wq);
    cudaGetSymbolAddress((void**)&pwk, r_wk);
    cudaGetSymbolAddress((void**)&pwv, r_wv);
    cudaGetSymbolAddress((void**)&pwo, r_wo);

    static int attr_set = 0;
    const int attn_smem = AT_SMEM_WORDS * 4;
    if (!attr_set) {
        cudaFuncSetAttribute(attn_mma_kernel,
                             cudaFuncAttributeMaxDynamicSharedMemorySize, attn_smem);
        cudaFuncSetAttribute(tf32_gemm,
                             cudaFuncAttributeMaxDynamicSharedMemorySize, GEMM_SMEM);
        cudaFuncSetAttribute(moe13_gemm,
                             cudaFuncAttributeMaxDynamicSharedMemorySize, MOE_SMEM);
        attr_set = 1;
    }

    roundcopy<<<(Dm*Dm/4 + 255)/256, 256>>>(w_q, pwq, Dm*Dm/4);
    roundcopy<<<(Dm*KVD/4 + 255)/256, 256>>>(w_k, pwk, Dm*KVD/4);
    roundcopy<<<(Dm*KVD/4 + 255)/256, 256>>>(w_v, pwv, Dm*KVD/4);
    roundcopy<<<(Dm*Dm/4 + 255)/256, 256>>>(w_o, pwo, Dm*Dm/4);

    zero_kernel<<<1, 32>>>();
    rmsnorm_kernel<<<Ttok, 256>>>(x, attn_norm_w, ph);
    tf32_gemm<<<dim3(Dm/128, Ttok/128, 1), 256, GEMM_SMEM>>>(ph, pwq, pq, Ttok, Dm, Dm,
                                                  nullptr, 0, nullptr, nullptr);
    tf32_gemm<<<dim3(KVD/128, Ttok/128, 2), 256, GEMM_SMEM>>>(ph, pwk, pk, Ttok, KVD, Dm,
                                                   nullptr, 0, pwv, pv);
    {
        int tot = Ttok*NH*(HDv/2) + Ttok*KVHv*(HDv/2) + Ttok*(KVD/2);
        rope_kernel<<<(tot + 255)/256, 256>>>();
    }
    attn_mma_kernel<<<dim3(Lq/64, NH, Bq), 128, attn_smem>>>();
    tf32_gemm<<<dim3(Dm/128, Ttok/128, 1), 256, GEMM_SMEM>>>(pao, pwo, out, Ttok, Dm, Dm,
                                                  x, 0, nullptr, nullptr);
    rmsnorm_kernel<<<Ttok, 256>>>(out, moe_norm_w, ph);
    gate_kernel<<<Ttok, 256>>>(gate_w);
    finalize_gate_kernel<<<1, 256>>>(out + (size_t)Ttok*Dm);
    scatter_kernel<<<(Ttok + 255)/256, 256>>>();
    moe13_gemm<<<dim3(NI/64, SLOTS/128, NE), 256, MOE_SMEM>>>(w1, w3);
    // w2 down-proj: atomicAdd weighted expert output directly into out
    tf32_gemm<<<dim3(Dm/128, SLOTS/128, NE), 256, GEMM_SMEM>>>(pg, w2, out, 0, Dm, NI,
                                                    nullptr, 3, nullptr, nullptr);
}